// round 11
// baseline (speedup 1.0000x reference)
#include <cuda_runtime.h>
#include <cstdint>

static constexpr int NIMG = 8192;
static constexpr int PIX  = 81;
static constexpr int BATCH = 64;
static constexpr int ENCF = 128;
static constexpr int KDIM = 10368;
static constexpr float BN_EPS = 1e-5f;
static constexpr float INV_CNT = 1.0f / (8192.0f * 81.0f);

__device__ float d_conv1[NIMG * 32 * PIX];
__device__ float d_conv2[NIMG * 64 * PIX];
__device__ float d_conv3[NIMG * 128 * PIX];
__device__ float d_part[2 * NIMG * ENCF];
__device__ float d_xcat1[BATCH * 384 * 128];
__device__ float d_xcat2[BATCH * 384 * 128];
__device__ float d_xg2[BATCH * 128 * 128];
__device__ float d_gsum[384];
__device__ float d_gsq[384];
__device__ float d_bnA[384];
__device__ float d_bnB[384];
__device__ uint4 d_a2h[4 * 18 * 32];
__device__ uint4 d_a2l[4 * 18 * 32];
__device__ uint4 d_a3h[8 * 36 * 32];
__device__ uint4 d_a3l[8 * 36 * 32];
__device__ uint4 d_aeh[8 * 648 * 32];
__device__ uint4 d_ael[8 * 648 * 32];
__device__ uint32_t d_bhi[NIMG * 5184];
__device__ uint32_t d_blo[NIMG * 5184];

// ---------- bf16 bit helpers ----------
__device__ __forceinline__ uint32_t f2bf(float f) {
    uint32_t u = __float_as_uint(f);
    return (u + 0x7FFFu + ((u >> 16) & 1u)) >> 16;
}
__device__ __forceinline__ float bf2f(uint32_t h) { return __uint_as_float(h << 16); }

// ---------- f32x2 helpers ----------
__device__ __forceinline__ unsigned long long pk2(float lo, float hi) {
    unsigned long long r; asm("mov.b64 %0, {%1, %2};" : "=l"(r) : "f"(lo), "f"(hi)); return r;
}
__device__ __forceinline__ unsigned long long bc2(float v) {
    unsigned long long r; asm("mov.b64 %0, {%1, %1};" : "=l"(r) : "f"(v)); return r;
}
__device__ __forceinline__ void fma2(unsigned long long& d, unsigned long long a, unsigned long long b) {
    asm("fma.rn.f32x2 %0, %1, %2, %0;" : "+l"(d) : "l"(a), "l"(b));
}
__device__ __forceinline__ void add2(unsigned long long& d, unsigned long long a) {
    asm("add.rn.f32x2 %0, %0, %1;" : "+l"(d) : "l"(a));
}
__device__ __forceinline__ float2 upk2(unsigned long long v) {
    float lo, hi; asm("mov.b64 {%0, %1}, %2;" : "=f"(lo), "=f"(hi) : "l"(v)); return make_float2(lo, hi);
}

// ---------- warp mma m16n8k16 bf16 ----------
__device__ __forceinline__ void mma16816(float* c, uint32_t a0, uint32_t a1, uint32_t a2,
                                         uint32_t a3, uint32_t b0, uint32_t b1) {
    asm volatile("mma.sync.aligned.m16n8k16.row.col.f32.bf16.bf16.f32 "
                 "{%0,%1,%2,%3}, {%4,%5,%6,%7}, {%8,%9}, {%0,%1,%2,%3};"
                 : "+f"(c[0]), "+f"(c[1]), "+f"(c[2]), "+f"(c[3])
                 : "r"(a0), "r"(a1), "r"(a2), "r"(a3), "r"(b0), "r"(b1));
}

// ---------- prepack weights into mma A-fragment order ----------
__global__ void prepack_frag_kernel(const float* __restrict__ w, uint4* __restrict__ ah,
                                    uint4* __restrict__ al, int CT, int NS, int KREAL) {
    int t = blockIdx.x * 256 + threadIdx.x;
    if (t >= CT * NS * 32) return;
    int lane = t & 31, s = (t >> 5) % NS, ct = t / (NS * 32);
    uint32_t vh[4], vl[4];
#pragma unroll
    for (int i = 0; i < 4; i++) {
        int co = ct * 16 + (lane >> 2) + (i & 1) * 8;
        int k = s * 16 + (lane & 3) * 2 + (i >> 1) * 8;
        float w0 = w[co * KREAL + k], w1 = w[co * KREAL + k + 1];
        uint32_t h0 = f2bf(w0), h1 = f2bf(w1);
        uint32_t l0 = f2bf(w0 - bf2f(h0)), l1 = f2bf(w1 - bf2f(h1));
        vh[i] = h0 | (h1 << 16);
        vl[i] = l0 | (l1 << 16);
    }
    ah[t] = make_uint4(vh[0], vh[1], vh[2], vh[3]);
    al[t] = make_uint4(vl[0], vl[1], vl[2], vl[3]);
}

// ---------- conv via warp mma: double-buffered plane prefetch ----------
template <int CIN, int COUT, int NS, int NTMAX, int OCC>
__global__ void __launch_bounds__(256, OCC) conv_mma_kernel(
    const float* __restrict__ gin, const uint4* __restrict__ afh, const uint4* __restrict__ afl,
    const float* __restrict__ bnA, const float* __restrict__ bnB,
    float* __restrict__ gout, float* __restrict__ gsum, float* __restrict__ gsq) {
    constexpr int KREAL = CIN * 9;
    constexpr int CT = COUT / 16;
    constexpr int NS2 = NS / 2;
    constexpr int NROW = 88;
    constexpr int BROW = 12;
    constexpr int BSTG = NROW * BROW;
    constexpr int BSTG2 = 2 * BSTG;
    constexpr int PL = CIN * 121;
    constexpr int OFF_PC0  = 2 * 2 * BSTG2 * 4;    // 33792
    constexpr int OFF_PC1  = OFF_PC0 + PL * 4;
    constexpr int OFF_OFSP = OFF_PC1 + PL * 4;
    constexpr int OFF_POF  = OFF_OFSP + (KREAL / 2) * 4;
    constexpr int OFF_RED  = OFF_POF + NROW * 2;
    extern __shared__ char smc[];
    uint32_t* Bs = (uint32_t*)smc;
    uint32_t* pc0  = (uint32_t*)(smc + OFF_PC0);
    uint32_t* pc1  = (uint32_t*)(smc + OFF_PC1);
    uint32_t* ofsp = (uint32_t*)(smc + OFF_OFSP);
    unsigned short* pofs = (unsigned short*)(smc + OFF_POF);
    float* red = (float*)(smc + OFF_RED);
    const int tid = threadIdx.x, wid = tid >> 5, lane = tid & 31;
    const int g = lane >> 2, tg = lane & 3;
    const int ct  = (CT == 8) ? wid : (wid & 3);
    const int ntb = (CT == 8) ? 0 : ((wid >> 2) * 6);
    const int ntn = (CT == 8) ? 11 : ((wid >> 2) ? 5 : 6);

    for (int k2 = tid; k2 < KREAL / 2; k2 += 256) {
        int k = 2 * k2;
        int ci0 = k / 9, r0 = k - ci0 * 9;
        int ci1 = (k + 1) / 9, r1 = (k + 1) - ci1 * 9;
        uint32_t o0 = ci0 * 121 + (r0 / 3) * 11 + (r0 % 3);
        uint32_t o1 = ci1 * 121 + (r1 / 3) * 11 + (r1 % 3);
        ofsp[k2] = o0 | (o1 << 16);
    }
    for (int p = tid; p < NROW; p += 256) {
        unsigned short v = 0;
        if (p < 81) { int py = p / 9, px = p - py * 9; v = (unsigned short)(py * 11 + px); }
        pofs[p] = v;
    }
    for (int i = tid; i < PL; i += 256) { pc0[i] = 0; pc1[i] = 0; }

    // division-free plane load with BN+ReLU -> packed bf16 hi|lo
    auto load_plane = [&](int img, uint32_t* dstb) {
        const float* ip = gin + (long long)img * (CIN * 81);
        for (int ch = wid; ch < CIN; ch += 8) {
            const float* cp = ip + ch * 81;
            uint32_t* dst = dstb + ch * 121;
            float a = bnA[ch], bb = bnB[ch];
            for (int p = lane; p < 81; p += 32) {
                int py = p / 9, px = p - py * 9;
                float v = fmaxf(fmaf(a, cp[p], bb), 0.f);
                uint32_t h = f2bf(v);
                uint32_t l = f2bf(v - bf2f(h));
                dst[(py + 1) * 11 + px + 1] = h | (l << 16);
            }
        }
    };

    float s0 = 0.f, q0 = 0.f, s1 = 0.f, q1 = 0.f;
    const int co0 = ct * 16 + g, co1 = co0 + 8;

    int parity = 0;
    load_plane(blockIdx.x, pc0);
    __syncthreads();

    for (int img = blockIdx.x; img < NIMG; img += gridDim.x) {
        uint32_t* cur = parity ? pc1 : pc0;
        uint32_t* nxt = parity ? pc0 : pc1;
        const int img2 = img + gridDim.x;

        float acc[NTMAX][4];
#pragma unroll
        for (int nt = 0; nt < NTMAX; nt++)
#pragma unroll
            for (int i = 0; i < 4; i++) acc[nt][i] = 0.f;

        auto build = [&](int S, int st) {
            uint32_t* bh = Bs + (st * 2 + 0) * BSTG2;
            uint32_t* bl = Bs + (st * 2 + 1) * BSTG2;
            for (int e = tid; e < NROW * 16; e += 256) {
                int p = e >> 4, kp = e & 15;
                uint32_t bhw = 0, blw = 0;
                if (p < 81) {
                    uint32_t op = ofsp[S * 16 + kp];
                    uint32_t pp = pofs[p];
                    uint32_t v0 = cur[(op & 0xFFFFu) + pp];
                    uint32_t v1 = cur[(op >> 16) + pp];
                    bhw = __byte_perm(v0, v1, 0x5410);
                    blw = __byte_perm(v0, v1, 0x7632);
                }
                int sub = kp >> 3, kq = kp & 7;
                uint32_t off = sub * BSTG + p * BROW + kq;
                bh[off] = bhw;
                bl[off] = blw;
            }
        };

        build(0, 0);
        __syncthreads();

        for (int S = 0; S < NS2; S++) {
            if (S == 0 && img2 < NIMG) load_plane(img2, nxt);   // overlapped prefetch
            if (S + 1 < NS2) build(S + 1, (S + 1) & 1);
            const uint32_t* cbh = Bs + ((S & 1) * 2 + 0) * BSTG2;
            const uint32_t* cbl = Bs + ((S & 1) * 2 + 1) * BSTG2;
#pragma unroll
            for (int sub = 0; sub < 2; sub++) {
                int s = S * 2 + sub;
                uint4 Ah = afh[(ct * NS + s) * 32 + lane];
                uint4 Al = afl[(ct * NS + s) * 32 + lane];
                const uint32_t* bh = cbh + sub * BSTG;
                const uint32_t* bl = cbl + sub * BSTG;
#pragma unroll
                for (int nt = 0; nt < NTMAX; nt++) {
                    if (nt < ntn) {
                        int row = ((ntb + nt) * 8 + g) * BROW;
                        uint32_t b0 = bh[row + tg], b1 = bh[row + 4 + tg];
                        mma16816(acc[nt], Ah.x, Ah.y, Ah.z, Ah.w, b0, b1);
                        mma16816(acc[nt], Al.x, Al.y, Al.z, Al.w, b0, b1);
                        uint32_t c0 = bl[row + tg], c1 = bl[row + 4 + tg];
                        mma16816(acc[nt], Ah.x, Ah.y, Ah.z, Ah.w, c0, c1);
                    }
                }
            }
            __syncthreads();
        }

        {
            float* op0 = gout + ((long long)img * COUT + co0) * 81;
            float* op1 = gout + ((long long)img * COUT + co1) * 81;
#pragma unroll
            for (int nt = 0; nt < NTMAX; nt++) {
                if (nt < ntn) {
                    int px = (ntb + nt) * 8 + tg * 2;
                    if (px < 81) {
                        op0[px] = acc[nt][0]; s0 += acc[nt][0]; q0 += acc[nt][0] * acc[nt][0];
                        op1[px] = acc[nt][2]; s1 += acc[nt][2]; q1 += acc[nt][2] * acc[nt][2];
                    }
                    if (px + 1 < 81) {
                        op0[px + 1] = acc[nt][1]; s0 += acc[nt][1]; q0 += acc[nt][1] * acc[nt][1];
                        op1[px + 1] = acc[nt][3]; s1 += acc[nt][3]; q1 += acc[nt][3] * acc[nt][3];
                    }
                }
            }
        }
        parity ^= 1;
    }

    __syncthreads();
    for (int i = tid; i < 2 * COUT; i += 256) red[i] = 0.f;
    __syncthreads();
    atomicAdd(&red[co0], s0); atomicAdd(&red[COUT + co0], q0);
    atomicAdd(&red[co1], s1); atomicAdd(&red[COUT + co1], q1);
    __syncthreads();
    for (int i = tid; i < COUT; i += 256) {
        atomicAdd(&gsum[i], red[i]);
        atomicAdd(&gsq[i], red[COUT + i]);
    }
}

// ---------- conv1 SIMT (f32x2, fused stats) ----------
template <int CIN, int COUT_T, int CG, int IPB>
__global__ void conv_bn_stats_kernel(const float* __restrict__ gin, const float* __restrict__ gw,
                                     float* __restrict__ gout, float* __restrict__ gsum,
                                     float* __restrict__ gsq, int cout_total) {
    constexpr int TASKS = (COUT_T / CG) * 9;
    constexpr int WROW = CIN * 9;
    constexpr int WSTR = (WROW % 2 == 0) ? (WROW + 1) : (WROW + 2);
    constexpr int CG2 = CG / 2;
    extern __shared__ float smf[];
    float* w_s = smf;
    float* in_s = w_s + COUT_T * WSTR;
    float* red = in_s + IPB * CIN * 121;

    const int tx = threadIdx.x, ty = threadIdx.y;
    const int tid = ty * TASKS + tx, nthr = TASKS * IPB;
    const int img = blockIdx.x * IPB + ty;
    const int co_base = blockIdx.y * COUT_T;

    for (int idx = tid; idx < COUT_T * WROW; idx += nthr) {
        int c = idx / WROW, r = idx - c * WROW;
        w_s[c * WSTR + r] = gw[(co_base + c) * WROW + r];
    }
    for (int idx = tid; idx < 2 * COUT_T; idx += nthr) red[idx] = 0.f;
    for (int idx = tid; idx < IPB * CIN * 121; idx += nthr) in_s[idx] = 0.f;
    __syncthreads();
    {
        const float* ip = gin + (long long)img * (CIN * 81);
        float* is = in_s + ty * (CIN * 121);
        for (int idx = tx; idx < CIN * 81; idx += TASKS) {
            int ch = idx / 81, p = idx - ch * 81, y = p / 9, x = p - y * 9;
            is[ch * 121 + (y + 1) * 11 + (x + 1)] = ip[idx];
        }
    }
    __syncthreads();

    const int grp = tx / 9, y = tx - grp * 9;
    unsigned long long acc2[CG2][9];
#pragma unroll
    for (int j = 0; j < CG2; j++)
#pragma unroll
        for (int x = 0; x < 9; x++) acc2[j][x] = 0ull;

    const float* is = in_s + ty * (CIN * 121);
    for (int ci = 0; ci < CIN; ci++) {
        const float* rp = is + ci * 121 + y * 11;
        unsigned long long b0[11], b1[11], b2[11];
#pragma unroll
        for (int x = 0; x < 11; x++) { b0[x] = bc2(rp[x]); b1[x] = bc2(rp[11 + x]); b2[x] = bc2(rp[22 + x]); }
#pragma unroll
        for (int j = 0; j < CG2; j++) {
            const float* wp = w_s + (grp * CG + 2 * j) * WSTR + ci * 9;
            const float* wq = wp + WSTR;
            unsigned long long w[9];
#pragma unroll
            for (int t = 0; t < 9; t++) w[t] = pk2(wp[t], wq[t]);
#pragma unroll
            for (int x = 0; x < 9; x++) {
                fma2(acc2[j][x], b0[x], w[0]); fma2(acc2[j][x], b0[x + 1], w[1]); fma2(acc2[j][x], b0[x + 2], w[2]);
                fma2(acc2[j][x], b1[x], w[3]); fma2(acc2[j][x], b1[x + 1], w[4]); fma2(acc2[j][x], b1[x + 2], w[5]);
                fma2(acc2[j][x], b2[x], w[6]); fma2(acc2[j][x], b2[x + 1], w[7]); fma2(acc2[j][x], b2[x + 2], w[8]);
            }
        }
    }
#pragma unroll
    for (int j = 0; j < CG2; j++) {
        int co0 = co_base + grp * CG + 2 * j;
        float* op0 = gout + ((long long)img * cout_total + co0) * 81 + y * 9;
        float* op1 = op0 + 81;
        unsigned long long s2 = 0ull, q2 = 0ull;
#pragma unroll
        for (int x = 0; x < 9; x++) {
            unsigned long long v = acc2[j][x];
            float2 f = upk2(v);
            op0[x] = f.x; op1[x] = f.y;
            add2(s2, v); fma2(q2, v, v);
        }
        float2 s = upk2(s2), q = upk2(q2);
        atomicAdd(&red[grp * CG + 2 * j], s.x);
        atomicAdd(&red[grp * CG + 2 * j + 1], s.y);
        atomicAdd(&red[COUT_T + grp * CG + 2 * j], q.x);
        atomicAdd(&red[COUT_T + grp * CG + 2 * j + 1], q.y);
    }
    __syncthreads();
    for (int idx = tid; idx < COUT_T; idx += nthr) {
        atomicAdd(&gsum[co_base + idx], red[idx]);
        atomicAdd(&gsq[co_base + idx], red[COUT_T + idx]);
    }
}

// ---------- BN helpers ----------
__global__ void zero_stats_kernel(float* gsum, float* gsq) {
    int t = threadIdx.x;
    if (t < 384) { gsum[t] = 0.f; gsq[t] = 0.f; }
}
__global__ void bn_prep_kernel(const float* gsum, const float* gsq, const float* gamma,
                               const float* beta, float* a, float* b, int C) {
    int c = threadIdx.x;
    if (c < C) {
        float mu = gsum[c] * INV_CNT;
        float var = gsq[c] * INV_CNT - mu * mu;
        float ai = gamma[c] * rsqrtf(var + BN_EPS);
        a[c] = ai; b[c] = beta[c] - mu * ai;
    }
}

// ---------- conv3 -> bf16 hi/lo pairs with BN+ReLU (slot-permuted) ----------
__global__ void bf16cvt_kernel(const float* __restrict__ x, const float* __restrict__ bnA,
                               const float* __restrict__ bnB, uint32_t* __restrict__ hi,
                               uint32_t* __restrict__ lo) {
    int idx = blockIdx.x * 256 + threadIdx.x;
    if (idx >= NIMG * 5184) return;
    int img = idx / 5184, kp = idx - img * 5184;
    int k0 = kp * 2;
    int ch0 = k0 / 81, ch1 = (k0 + 1) / 81;
    const float* row = x + (long long)img * KDIM;
    float v0 = fmaxf(fmaf(bnA[ch0], row[k0], bnB[ch0]), 0.f);
    float v1 = fmaxf(fmaf(bnA[ch1], row[k0 + 1], bnB[ch1]), 0.f);
    uint32_t h0 = f2bf(v0), h1 = f2bf(v1);
    uint32_t l0 = f2bf(v0 - bf2f(h0)), l1 = f2bf(v1 - bf2f(h1));
    int lp = kp & 7;
    int dst = img * 5184 + (kp & ~7) + (lp & 3) * 2 + (lp >> 2);
    hi[dst] = h0 | (h1 << 16);
    lo[dst] = l0 | (l1 << 16);
}

// ---------- encoder GEMM via mma, split-K=2 ----------
__global__ void __launch_bounds__(256) enc_mma_kernel(
    const uint32_t* __restrict__ bhig, const uint32_t* __restrict__ blog,
    const uint4* __restrict__ afh, const uint4* __restrict__ afl,
    float* __restrict__ part) {
    __shared__ uint32_t Bs[2][2][64][8];
    const int tid = threadIdx.x, wid = tid >> 5, lane = tid & 31;
    const int g = lane >> 2, tg = lane & 3;
    const int m0 = (blockIdx.x & 127) * 64;
    const int ks = blockIdx.x >> 7;
    const int sbase = ks * 324;

    float acc[8][4];
#pragma unroll
    for (int nt = 0; nt < 8; nt++)
#pragma unroll
        for (int i = 0; i < 4; i++) acc[nt][i] = 0.f;

    const int lrow = (tid & 127) >> 1, lhalf = tid & 1, lterm = tid >> 7;
    const uint32_t* lsrc = (lterm == 0 ? bhig : blog) + (size_t)(m0 + lrow) * 5184
                           + sbase * 8 + lhalf * 4;

    *(uint4*)&Bs[0][lterm][lrow][lhalf * 4] = *(const uint4*)(lsrc);
    __syncthreads();

    uint4 Ah = afh[(wid * 648 + sbase) * 32 + lane];
    uint4 Al = afl[(wid * 648 + sbase) * 32 + lane];

    for (int s = 0; s < 324; s++) {
        int st = s & 1;
        if (s + 1 < 324)
            *(uint4*)&Bs[st ^ 1][lterm][lrow][lhalf * 4] = *(const uint4*)(lsrc + (s + 1) * 8);
        uint4 Ah2, Al2;
        if (s + 1 < 324) {
            Ah2 = afh[(wid * 648 + sbase + s + 1) * 32 + lane];
            Al2 = afl[(wid * 648 + sbase + s + 1) * 32 + lane];
        }
#pragma unroll
        for (int nt = 0; nt < 8; nt++) {
            int col = nt * 8 + g;
            uint2 bh = *(const uint2*)&Bs[st][0][col][tg * 2];
            uint2 bl = *(const uint2*)&Bs[st][1][col][tg * 2];
            mma16816(acc[nt], Ah.x, Ah.y, Ah.z, Ah.w, bh.x, bh.y);
            mma16816(acc[nt], Al.x, Al.y, Al.z, Al.w, bh.x, bh.y);
            mma16816(acc[nt], Ah.x, Ah.y, Ah.z, Ah.w, bl.x, bl.y);
        }
        Ah = Ah2; Al = Al2;
        __syncthreads();
    }

    const int e0 = wid * 16 + g, e1 = e0 + 8;
    float* pp = part + ks * (NIMG * ENCF);
#pragma unroll
    for (int nt = 0; nt < 8; nt++) {
        int n = nt * 8 + tg * 2;
        pp[(m0 + n) * ENCF + e0]     = acc[nt][0];
        pp[(m0 + n + 1) * ENCF + e0] = acc[nt][1];
        pp[(m0 + n) * ENCF + e1]     = acc[nt][2];
        pp[(m0 + n + 1) * ENCF + e1] = acc[nt][3];
    }
}

__global__ void combine_enc_kernel(const float* __restrict__ part, const float* __restrict__ enc_b,
                                   float* __restrict__ xcat) {
    int idx = blockIdx.x * 256 + threadIdx.x;
    int e = idx & 127, m = idx >> 7, b = m >> 7, n = m & 127;
    float v = part[idx] + part[NIMG * ENCF + idx] + enc_b[e];
    xcat[b * (384 * 128) + e * 128 + n] = v;
}

// ---------- X*S and X*S^2 (f-rows split across 2 blocks per batch) ----------
__global__ void xs_kernel(float* __restrict__ xcat, const float* __restrict__ gso) {
    extern __shared__ float smf[];
    float (*Xs)[129] = (float (*)[129])smf;
    float (*Ss)[129] = (float (*)[129])(smf + 64 * 129);
    const int b = blockIdx.x >> 1, fh = blockIdx.x & 1;
    const int tx = threadIdx.x;
    for (int l = 0; l < 64; l++) {
        int idx = tx + l * 256, r = idx >> 7, c = idx & 127;
        Ss[r][c] = gso[b * 16384 + idx];
    }
    for (int l = 0; l < 32; l++) {
        int idx = tx + l * 256, r = idx >> 7, c = idx & 127;
        Xs[r][c] = xcat[b * (384 * 128) + (fh * 64 + r) * 128 + c];
    }
    __syncthreads();
    const int nj = tx & 15, fi = tx >> 4;
    unsigned long long acc2[4][4];
    for (int pass = 0; pass < 2; pass++) {
#pragma unroll
        for (int i = 0; i < 4; i++)
#pragma unroll
            for (int j = 0; j < 4; j++) acc2[i][j] = 0ull;
        for (int n = 0; n < 128; n++) {
            unsigned long long sp[4];
#pragma unroll
            for (int j = 0; j < 4; j++) sp[j] = pk2(Ss[n][nj + 32 * j], Ss[n][nj + 16 + 32 * j]);
#pragma unroll
            for (int i = 0; i < 4; i++) {
                unsigned long long xb = bc2(Xs[fi + 16 * i][n]);
#pragma unroll
                for (int j = 0; j < 4; j++) fma2(acc2[i][j], xb, sp[j]);
            }
        }
        __syncthreads();
        float* gdst = xcat + b * (384 * 128) + (pass + 1) * 16384 + fh * 64 * 128;
#pragma unroll
        for (int i = 0; i < 4; i++)
#pragma unroll
            for (int j = 0; j < 4; j++) {
                float2 v = upk2(acc2[i][j]);
                int f = fi + 16 * i;
                Xs[f][nj + 32 * j] = v.x; Xs[f][nj + 16 + 32 * j] = v.y;
                gdst[f * 128 + nj + 32 * j] = v.x;
                gdst[f * 128 + nj + 16 + 32 * j] = v.y;
            }
        __syncthreads();
    }
}

// ---------- graph-filter GEMM (2 blocks per batch) ----------
__global__ void gfilter_kernel(const float* __restrict__ xcat, const float* __restrict__ W,
                               const float* __restrict__ bias, float* __restrict__ out,
                               int out_stride) {
    extern __shared__ float smf[];
    float (*Ws)[97] = (float (*)[97])smf;
    float (*Xs)[129] = (float (*)[129])(smf + 64 * 97);
    const int b = blockIdx.x >> 1, half = blockIdx.x & 1;
    const int tx = threadIdx.x;
    const int nj = tx & 15, gi = tx >> 4;
    unsigned long long acc2[4][4];
#pragma unroll
    for (int i = 0; i < 4; i++)
#pragma unroll
        for (int j = 0; j < 4; j++) acc2[i][j] = 0ull;
    for (int kt = 0; kt < 4; kt++) {
        for (int l = 0; l < 24; l++) {
            int idx = tx + l * 256;
            int g = idx / 96, kc = idx - g * 96;
            int kg = kt * 96 + kc;
            Ws[g][kc] = W[(kg >> 7) * 16384 + (half * 64 + g) * 128 + (kg & 127)];
        }
        for (int l = 0; l < 48; l++) {
            int idx = tx + l * 256, r = idx >> 7, c = idx & 127;
            Xs[r][c] = xcat[b * (384 * 128) + (kt * 96 + r) * 128 + c];
        }
        __syncthreads();
        for (int kc = 0; kc < 96; kc++) {
            unsigned long long xp[4];
#pragma unroll
            for (int j = 0; j < 4; j++) xp[j] = pk2(Xs[kc][nj + 32 * j], Xs[kc][nj + 16 + 32 * j]);
#pragma unroll
            for (int i = 0; i < 4; i++) {
                unsigned long long wb = bc2(Ws[gi + 16 * i][kc]);
#pragma unroll
                for (int j = 0; j < 4; j++) fma2(acc2[i][j], wb, xp[j]);
            }
        }
        __syncthreads();
    }
#pragma unroll
    for (int i = 0; i < 4; i++) {
        int g = half * 64 + gi + 16 * i;
        float bb = bias[g];
#pragma unroll
        for (int j = 0; j < 4; j++) {
            float2 v = upk2(acc2[i][j]);
            out[b * out_stride + g * 128 + nj + 32 * j] = fmaxf(v.x + bb, 0.f);
            out[b * out_stride + g * 128 + nj + 16 + 32 * j] = fmaxf(v.y + bb, 0.f);
        }
    }
}

// ---------- action head ----------
__global__ void act_kernel(const float* __restrict__ xg2, const float* __restrict__ aw,
                           const float* __restrict__ ab, float* __restrict__ out) {
    extern __shared__ float smf[];
    float* xs = smf;
    float* ws = smf + 16384;
    const int b = blockIdx.x, t = threadIdx.x;
    for (int i = t; i < 16384; i += 256) xs[i] = xg2[b * 16384 + i];
    for (int i = t; i < 640; i += 256) ws[i] = aw[i];
    __syncthreads();
    for (int o = t; o < 640; o += 256) {
        int a = o % 5, n = o / 5;
        float s = ab[a];
        const float* wp = ws + a * 128;
        const float* xp = xs + n;
#pragma unroll 8
        for (int g = 0; g < 128; g++) s = fmaf(xp[g * 128], wp[g], s);
        out[b * 640 + o] = s;
    }
}

// ---------- host launcher ----------
extern "C" void kernel_launch(void* const* d_in, const int* in_sizes, int n_in,
                              void* d_out, int out_size) {
    (void)in_sizes; (void)n_in; (void)out_size;
    const float* states = (const float*)d_in[0];
    const float* gso = (const float*)d_in[1];
    const float* c1_w = (const float*)d_in[2];
    const float* c1_g = (const float*)d_in[4];
    const float* c1_be = (const float*)d_in[5];
    const float* c2_w = (const float*)d_in[6];
    const float* c2_g = (const float*)d_in[8];
    const float* c2_be = (const float*)d_in[9];
    const float* c3_w = (const float*)d_in[10];
    const float* c3_g = (const float*)d_in[12];
    const float* c3_be = (const float*)d_in[13];
    const float* enc_w = (const float*)d_in[14];
    const float* enc_b = (const float*)d_in[15];
    const float* g1_w = (const float*)d_in[16];
    const float* g1_b = (const float*)d_in[17];
    const float* g2_w = (const float*)d_in[18];
    const float* g2_b = (const float*)d_in[19];
    const float* act_w = (const float*)d_in[20];
    const float* act_b = (const float*)d_in[21];
    float* out = (float*)d_out;

    void *p1, *p2, *p3, *pp, *px1, *px2, *pg2, *ps, *pq, *pa, *pb;
    void *a2h, *a2l, *a3h, *a3l, *aeh, *ael, *bhi, *blo;
    cudaGetSymbolAddress(&p1, d_conv1);  cudaGetSymbolAddress(&p2, d_conv2);
    cudaGetSymbolAddress(&p3, d_conv3);  cudaGetSymbolAddress(&pp, d_part);
    cudaGetSymbolAddress(&px1, d_xcat1); cudaGetSymbolAddress(&px2, d_xcat2);
    cudaGetSymbolAddress(&pg2, d_xg2);   cudaGetSymbolAddress(&ps, d_gsum);
    cudaGetSymbolAddress(&pq, d_gsq);    cudaGetSymbolAddress(&pa, d_bnA);
    cudaGetSymbolAddress(&pb, d_bnB);
    cudaGetSymbolAddress(&a2h, d_a2h);   cudaGetSymbolAddress(&a2l, d_a2l);
    cudaGetSymbolAddress(&a3h, d_a3h);   cudaGetSymbolAddress(&a3l, d_a3l);
    cudaGetSymbolAddress(&aeh, d_aeh);   cudaGetSymbolAddress(&ael, d_ael);
    cudaGetSymbolAddress(&bhi, d_bhi);   cudaGetSymbolAddress(&blo, d_blo);
    float *conv1 = (float*)p1, *conv2 = (float*)p2, *conv3 = (float*)p3;
    float *part = (float*)pp;
    float *xcat1 = (float*)px1, *xcat2 = (float*)px2, *xg2 = (float*)pg2;
    float *gsum = (float*)ps, *gsq = (float*)pq, *bnA = (float*)pa, *bnB = (float*)pb;

    const int SM1 = (32 * 29 + 2 * 3 * 121 + 64) * 4;
    // conv_mma smem: Bs 33792 + 2*pc(PL*4) + ofsp (KREAL/2)*4 + pofs 176 + red 2*COUT*4
    const int SMC2 = 33792 + 2 * (32 * 121 * 4) + 144 * 4 + 176 + 2 * 64 * 4;    // 66016
    const int SMC3 = 33792 + 2 * (64 * 121 * 4) + 288 * 4 + 176 + 2 * 128 * 4;   // 98192
    const int XS_SMEM = (64 * 129 + 128 * 129) * 4;
    const int GF_SMEM = (64 * 97 + 96 * 129) * 4;
    const int ACT_SMEM = (16384 + 640) * 4;

    cudaFuncSetAttribute(conv_bn_stats_kernel<3, 32, 4, 2>, cudaFuncAttributeMaxDynamicSharedMemorySize, SM1);
    cudaFuncSetAttribute(conv_mma_kernel<32, 64, 18, 6, 3>, cudaFuncAttributeMaxDynamicSharedMemorySize, SMC2);
    cudaFuncSetAttribute(conv_mma_kernel<64, 128, 36, 11, 2>, cudaFuncAttributeMaxDynamicSharedMemorySize, SMC3);
    cudaFuncSetAttribute(xs_kernel, cudaFuncAttributeMaxDynamicSharedMemorySize, XS_SMEM);
    cudaFuncSetAttribute(gfilter_kernel, cudaFuncAttributeMaxDynamicSharedMemorySize, GF_SMEM);
    cudaFuncSetAttribute(act_kernel, cudaFuncAttributeMaxDynamicSharedMemorySize, ACT_SMEM);

    zero_stats_kernel<<<1, 384>>>(gsum, gsq);
    prepack_frag_kernel<<<(4 * 18 * 32 + 255) / 256, 256>>>(c2_w, (uint4*)a2h, (uint4*)a2l, 4, 18, 288);
    prepack_frag_kernel<<<(8 * 36 * 32 + 255) / 256, 256>>>(c3_w, (uint4*)a3h, (uint4*)a3l, 8, 36, 576);
    prepack_frag_kernel<<<648, 256>>>(enc_w, (uint4*)aeh, (uint4*)ael, 8, 648, 10368);

    conv_bn_stats_kernel<3, 32, 4, 2>
        <<<dim3(NIMG / 2, 1), dim3(72, 2), SM1>>>(states, c1_w, conv1, gsum, gsq, 32);
    bn_prep_kernel<<<1, 128>>>(gsum, gsq, c1_g, c1_be, bnA, bnB, 32);

    conv_mma_kernel<32, 64, 18, 6, 3><<<444, 256, SMC2>>>(conv1, (const uint4*)a2h, (const uint4*)a2l,
                                                          bnA, bnB, conv2, gsum + 128, gsq + 128);
    bn_prep_kernel<<<1, 128>>>(gsum + 128, gsq + 128, c2_g, c2_be, bnA + 128, bnB + 128, 64);

    conv_mma_kernel<64, 128, 36, 11, 2><<<296, 256, SMC3>>>(conv2, (const uint4*)a3h, (const uint4*)a3l,
                                                            bnA + 128, bnB + 128, conv3,
                                                            gsum + 256, gsq + 256);
    bn_prep_kernel<<<1, 128>>>(gsum + 256, gsq + 256, c3_g, c3_be, bnA + 256, bnB + 256, 128);

    bf16cvt_kernel<<<(NIMG * 5184 + 255) / 256, 256>>>(conv3, bnA + 256, bnB + 256,
                                                       (uint32_t*)bhi, (uint32_t*)blo);
    enc_mma_kernel<<<256, 256>>>((const uint32_t*)bhi, (const uint32_t*)blo,
                                 (const uint4*)aeh, (const uint4*)ael, part);
    combine_enc_kernel<<<4096, 256>>>(part, enc_b, xcat1);

    xs_kernel<<<BATCH * 2, 256, XS_SMEM>>>(xcat1, gso);
    gfilter_kernel<<<BATCH * 2, 256, GF_SMEM>>>(xcat1, g1_w, g1_b, xcat2, 384 * 128);
    xs_kernel<<<BATCH * 2, 256, XS_SMEM>>>(xcat2, gso);
    gfilter_kernel<<<BATCH * 2, 256, GF_SMEM>>>(xcat2, g2_w, g2_b, xg2, 128 * 128);
    act_kernel<<<BATCH, 256, ACT_SMEM>>>(xg2, act_w, act_b, out);
}

// round 12
// speedup vs baseline: 1.0647x; 1.0647x over previous
#include <cuda_runtime.h>
#include <cstdint>

static constexpr int NIMG = 8192;
static constexpr int PIX  = 81;
static constexpr int BATCH = 64;
static constexpr int ENCF = 128;
static constexpr int KDIM = 10368;
static constexpr float BN_EPS = 1e-5f;
static constexpr float INV_CNT = 1.0f / (8192.0f * 81.0f);

__device__ float d_conv1[NIMG * 32 * PIX];
__device__ float d_conv2[NIMG * 64 * PIX];
__device__ float d_conv3[NIMG * 128 * PIX];
__device__ float d_part[2 * NIMG * ENCF];
__device__ float d_xcat1[BATCH * 384 * 128];
__device__ float d_xcat2[BATCH * 384 * 128];
__device__ float d_xg2[BATCH * 128 * 128];
__device__ float d_gsum[384];
__device__ float d_gsq[384];
__device__ float d_bnA[384];
__device__ float d_bnB[384];
__device__ uint4 d_a2h[4 * 18 * 32];
__device__ uint4 d_a2l[4 * 18 * 32];
__device__ uint4 d_a3h[8 * 36 * 32];
__device__ uint4 d_a3l[8 * 36 * 32];
__device__ uint4 d_aeh[8 * 648 * 32];
__device__ uint4 d_ael[8 * 648 * 32];
__device__ uint32_t d_bhi[NIMG * 5184];
__device__ uint32_t d_blo[NIMG * 5184];

// ---------- bf16 bit helpers ----------
__device__ __forceinline__ uint32_t f2bf(float f) {
    uint32_t u = __float_as_uint(f);
    return (u + 0x7FFFu + ((u >> 16) & 1u)) >> 16;
}
__device__ __forceinline__ float bf2f(uint32_t h) { return __uint_as_float(h << 16); }

// ---------- f32x2 helpers ----------
__device__ __forceinline__ unsigned long long pk2(float lo, float hi) {
    unsigned long long r; asm("mov.b64 %0, {%1, %2};" : "=l"(r) : "f"(lo), "f"(hi)); return r;
}
__device__ __forceinline__ unsigned long long bc2(float v) {
    unsigned long long r; asm("mov.b64 %0, {%1, %1};" : "=l"(r) : "f"(v)); return r;
}
__device__ __forceinline__ void fma2(unsigned long long& d, unsigned long long a, unsigned long long b) {
    asm("fma.rn.f32x2 %0, %1, %2, %0;" : "+l"(d) : "l"(a), "l"(b));
}
__device__ __forceinline__ void add2(unsigned long long& d, unsigned long long a) {
    asm("add.rn.f32x2 %0, %0, %1;" : "+l"(d) : "l"(a));
}
__device__ __forceinline__ float2 upk2(unsigned long long v) {
    float lo, hi; asm("mov.b64 {%0, %1}, %2;" : "=f"(lo), "=f"(hi) : "l"(v)); return make_float2(lo, hi);
}

// ---------- warp mma m16n8k16 bf16 ----------
__device__ __forceinline__ void mma16816(float* c, uint32_t a0, uint32_t a1, uint32_t a2,
                                         uint32_t a3, uint32_t b0, uint32_t b1) {
    asm volatile("mma.sync.aligned.m16n8k16.row.col.f32.bf16.bf16.f32 "
                 "{%0,%1,%2,%3}, {%4,%5,%6,%7}, {%8,%9}, {%0,%1,%2,%3};"
                 : "+f"(c[0]), "+f"(c[1]), "+f"(c[2]), "+f"(c[3])
                 : "r"(a0), "r"(a1), "r"(a2), "r"(a3), "r"(b0), "r"(b1));
}

// ---------- prepack weights into mma A-fragment order ----------
__global__ void prepack_frag_kernel(const float* __restrict__ w, uint4* __restrict__ ah,
                                    uint4* __restrict__ al, int CT, int NS, int KREAL) {
    int t = blockIdx.x * 256 + threadIdx.x;
    if (t >= CT * NS * 32) return;
    int lane = t & 31, s = (t >> 5) % NS, ct = t / (NS * 32);
    uint32_t vh[4], vl[4];
#pragma unroll
    for (int i = 0; i < 4; i++) {
        int co = ct * 16 + (lane >> 2) + (i & 1) * 8;
        int k = s * 16 + (lane & 3) * 2 + (i >> 1) * 8;
        float w0 = w[co * KREAL + k], w1 = w[co * KREAL + k + 1];
        uint32_t h0 = f2bf(w0), h1 = f2bf(w1);
        uint32_t l0 = f2bf(w0 - bf2f(h0)), l1 = f2bf(w1 - bf2f(h1));
        vh[i] = h0 | (h1 << 16);
        vl[i] = l0 | (l1 << 16);
    }
    ah[t] = make_uint4(vh[0], vh[1], vh[2], vh[3]);
    al[t] = make_uint4(vl[0], vl[1], vl[2], vl[3]);
}

// ---------- conv via warp mma: packed plane, pad rows pre-zeroed, 2 k-steps/barrier ----------
template <int CIN, int COUT, int NS, int NTMAX, int OCC>
__global__ void __launch_bounds__(256, OCC) conv_mma_kernel(
    const float* __restrict__ gin, const uint4* __restrict__ afh, const uint4* __restrict__ afl,
    const float* __restrict__ bnA, const float* __restrict__ bnB,
    float* __restrict__ gout, float* __restrict__ gsum, float* __restrict__ gsq) {
    constexpr int KREAL = CIN * 9;
    constexpr int CT = COUT / 16;
    constexpr int NS2 = NS / 2;
    constexpr int NROW = 88;
    constexpr int BROW = 12;
    constexpr int BSTG = NROW * BROW;
    constexpr int BSTG2 = 2 * BSTG;
    constexpr int PL = CIN * 121;
    constexpr int OFF_PC   = 2 * 2 * BSTG2 * 4;   // 33792
    constexpr int OFF_OFSP = OFF_PC + PL * 4;
    constexpr int OFF_POF  = OFF_OFSP + (KREAL / 2) * 4;
    constexpr int OFF_RED  = OFF_POF + 81 * 2 + 2;   // pofs only 81 entries (pad to 4B)
    extern __shared__ char smc[];
    uint32_t* Bs = (uint32_t*)smc;
    uint32_t* pc   = (uint32_t*)(smc + OFF_PC);
    uint32_t* ofsp = (uint32_t*)(smc + OFF_OFSP);
    unsigned short* pofs = (unsigned short*)(smc + OFF_POF);
    float* red = (float*)(smc + OFF_RED);
    const int tid = threadIdx.x, wid = tid >> 5, lane = tid & 31;
    const int g = lane >> 2, tg = lane & 3;
    const int ct  = (CT == 8) ? wid : (wid & 3);
    const int ntb = (CT == 8) ? 0 : ((wid >> 2) * 6);
    const int ntn = (CT == 8) ? 11 : ((wid >> 2) ? 5 : 6);

    for (int k2 = tid; k2 < KREAL / 2; k2 += 256) {
        int k = 2 * k2;
        int ci0 = k / 9, r0 = k - ci0 * 9;
        int ci1 = (k + 1) / 9, r1 = (k + 1) - ci1 * 9;
        uint32_t o0 = ci0 * 121 + (r0 / 3) * 11 + (r0 % 3);
        uint32_t o1 = ci1 * 121 + (r1 / 3) * 11 + (r1 % 3);
        ofsp[k2] = o0 | (o1 << 16);
    }
    for (int p = tid; p < 81; p += 256) {
        int py = p / 9, px = p - py * 9;
        pofs[p] = (unsigned short)(py * 11 + px);
    }
    for (int i = tid; i < PL; i += 256) pc[i] = 0;
    // pre-zero constant pad rows p=81..87 in ALL four stage buffers (never rewritten)
    for (int e = tid; e < 4 * 7 * 16; e += 256) {
        int st4 = e / (7 * 16);                // 0..3 over {stage,term} x {2 stages}
        int rem = e - st4 * 112;
        int p = 81 + rem / 16, kp = rem & 15;
        int sub = kp >> 3, kq = kp & 7;
        Bs[st4 * BSTG2 + sub * BSTG + p * BROW + kq] = 0u;
    }

    float s0 = 0.f, q0 = 0.f, s1 = 0.f, q1 = 0.f;
    const int co0 = ct * 16 + g, co1 = co0 + 8;

    for (int img = blockIdx.x; img < NIMG; img += gridDim.x) {
        __syncthreads();
        // division-free plane load with BN+ReLU -> packed bf16 hi|lo
        const float* ip = gin + (long long)img * (CIN * 81);
        for (int ch = wid; ch < CIN; ch += 8) {
            const float* cp = ip + ch * 81;
            uint32_t* dst = pc + ch * 121;
            float a = bnA[ch], bb = bnB[ch];
            for (int p = lane; p < 81; p += 32) {
                int py = p / 9, px = p - py * 9;
                float v = fmaxf(fmaf(a, cp[p], bb), 0.f);
                uint32_t h = f2bf(v);
                uint32_t l = f2bf(v - bf2f(h));
                dst[(py + 1) * 11 + px + 1] = h | (l << 16);
            }
        }
        __syncthreads();

        float acc[NTMAX][4];
#pragma unroll
        for (int nt = 0; nt < NTMAX; nt++)
#pragma unroll
            for (int i = 0; i < 4; i++) acc[nt][i] = 0.f;

        // build one 32-k chunk: only real rows p<81 (pad rows pre-zeroed)
        auto build = [&](int S, int st) {
            uint32_t* bh = Bs + (st * 2 + 0) * BSTG2;
            uint32_t* bl = Bs + (st * 2 + 1) * BSTG2;
            for (int e = tid; e < 81 * 16; e += 256) {
                int p = e >> 4, kp = e & 15;
                uint32_t op = ofsp[S * 16 + kp];
                uint32_t pp = pofs[p];
                uint32_t v0 = pc[(op & 0xFFFFu) + pp];
                uint32_t v1 = pc[(op >> 16) + pp];
                uint32_t bhw = __byte_perm(v0, v1, 0x5410);
                uint32_t blw = __byte_perm(v0, v1, 0x7632);
                int sub = kp >> 3, kq = kp & 7;
                uint32_t off = sub * BSTG + p * BROW + kq;
                bh[off] = bhw;
                bl[off] = blw;
            }
        };

        build(0, 0);
        __syncthreads();

        for (int S = 0; S < NS2; S++) {
            if (S + 1 < NS2) build(S + 1, (S + 1) & 1);
            const uint32_t* cbh = Bs + ((S & 1) * 2 + 0) * BSTG2;
            const uint32_t* cbl = Bs + ((S & 1) * 2 + 1) * BSTG2;
#pragma unroll
            for (int sub = 0; sub < 2; sub++) {
                int s = S * 2 + sub;
                uint4 Ah = afh[(ct * NS + s) * 32 + lane];
                uint4 Al = afl[(ct * NS + s) * 32 + lane];
                const uint32_t* bh = cbh + sub * BSTG;
                const uint32_t* bl = cbl + sub * BSTG;
#pragma unroll
                for (int nt = 0; nt < NTMAX; nt++) {
                    if (nt < ntn) {
                        int row = ((ntb + nt) * 8 + g) * BROW;
                        uint32_t b0 = bh[row + tg], b1 = bh[row + 4 + tg];
                        mma16816(acc[nt], Ah.x, Ah.y, Ah.z, Ah.w, b0, b1);
                        mma16816(acc[nt], Al.x, Al.y, Al.z, Al.w, b0, b1);
                        uint32_t c0 = bl[row + tg], c1 = bl[row + 4 + tg];
                        mma16816(acc[nt], Ah.x, Ah.y, Ah.z, Ah.w, c0, c1);
                    }
                }
            }
            __syncthreads();
        }

        {
            float* op0 = gout + ((long long)img * COUT + co0) * 81;
            float* op1 = gout + ((long long)img * COUT + co1) * 81;
#pragma unroll
            for (int nt = 0; nt < NTMAX; nt++) {
                if (nt < ntn) {
                    int px = (ntb + nt) * 8 + tg * 2;
                    if (px < 81) {
                        op0[px] = acc[nt][0]; s0 += acc[nt][0]; q0 += acc[nt][0] * acc[nt][0];
                        op1[px] = acc[nt][2]; s1 += acc[nt][2]; q1 += acc[nt][2] * acc[nt][2];
                    }
                    if (px + 1 < 81) {
                        op0[px + 1] = acc[nt][1]; s0 += acc[nt][1]; q0 += acc[nt][1] * acc[nt][1];
                        op1[px + 1] = acc[nt][3]; s1 += acc[nt][3]; q1 += acc[nt][3] * acc[nt][3];
                    }
                }
            }
        }
    }

    __syncthreads();
    for (int i = tid; i < 2 * COUT; i += 256) red[i] = 0.f;
    __syncthreads();
    atomicAdd(&red[co0], s0); atomicAdd(&red[COUT + co0], q0);
    atomicAdd(&red[co1], s1); atomicAdd(&red[COUT + co1], q1);
    __syncthreads();
    for (int i = tid; i < COUT; i += 256) {
        atomicAdd(&gsum[i], red[i]);
        atomicAdd(&gsq[i], red[COUT + i]);
    }
}

// ---------- conv1 SIMT (f32x2, fused stats; CG=2 for low reg pressure) ----------
template <int CIN, int COUT_T, int CG, int IPB>
__global__ void conv_bn_stats_kernel(const float* __restrict__ gin, const float* __restrict__ gw,
                                     float* __restrict__ gout, float* __restrict__ gsum,
                                     float* __restrict__ gsq, int cout_total) {
    constexpr int TASKS = (COUT_T / CG) * 9;
    constexpr int WROW = CIN * 9;
    constexpr int WSTR = (WROW % 2 == 0) ? (WROW + 1) : (WROW + 2);
    constexpr int CG2 = CG / 2;
    extern __shared__ float smf[];
    float* w_s = smf;
    float* in_s = w_s + COUT_T * WSTR;
    float* red = in_s + IPB * CIN * 121;

    const int tx = threadIdx.x, ty = threadIdx.y;
    const int tid = ty * TASKS + tx, nthr = TASKS * IPB;
    const int img = blockIdx.x * IPB + ty;
    const int co_base = blockIdx.y * COUT_T;

    for (int idx = tid; idx < COUT_T * WROW; idx += nthr) {
        int c = idx / WROW, r = idx - c * WROW;
        w_s[c * WSTR + r] = gw[(co_base + c) * WROW + r];
    }
    for (int idx = tid; idx < 2 * COUT_T; idx += nthr) red[idx] = 0.f;
    for (int idx = tid; idx < IPB * CIN * 121; idx += nthr) in_s[idx] = 0.f;
    __syncthreads();
    {
        const float* ip = gin + (long long)img * (CIN * 81);
        float* is = in_s + ty * (CIN * 121);
        for (int idx = tx; idx < CIN * 81; idx += TASKS) {
            int ch = idx / 81, p = idx - ch * 81, y = p / 9, x = p - y * 9;
            is[ch * 121 + (y + 1) * 11 + (x + 1)] = ip[idx];
        }
    }
    __syncthreads();

    const int grp = tx / 9, y = tx - grp * 9;
    unsigned long long acc2[CG2][9];
#pragma unroll
    for (int j = 0; j < CG2; j++)
#pragma unroll
        for (int x = 0; x < 9; x++) acc2[j][x] = 0ull;

    const float* is = in_s + ty * (CIN * 121);
    for (int ci = 0; ci < CIN; ci++) {
        const float* rp = is + ci * 121 + y * 11;
        unsigned long long b0[11], b1[11], b2[11];
#pragma unroll
        for (int x = 0; x < 11; x++) { b0[x] = bc2(rp[x]); b1[x] = bc2(rp[11 + x]); b2[x] = bc2(rp[22 + x]); }
#pragma unroll
        for (int j = 0; j < CG2; j++) {
            const float* wp = w_s + (grp * CG + 2 * j) * WSTR + ci * 9;
            const float* wq = wp + WSTR;
            unsigned long long w[9];
#pragma unroll
            for (int t = 0; t < 9; t++) w[t] = pk2(wp[t], wq[t]);
#pragma unroll
            for (int x = 0; x < 9; x++) {
                fma2(acc2[j][x], b0[x], w[0]); fma2(acc2[j][x], b0[x + 1], w[1]); fma2(acc2[j][x], b0[x + 2], w[2]);
                fma2(acc2[j][x], b1[x], w[3]); fma2(acc2[j][x], b1[x + 1], w[4]); fma2(acc2[j][x], b1[x + 2], w[5]);
                fma2(acc2[j][x], b2[x], w[6]); fma2(acc2[j][x], b2[x + 1], w[7]); fma2(acc2[j][x], b2[x + 2], w[8]);
            }
        }
    }
#pragma unroll
    for (int j = 0; j < CG2; j++) {
        int co0 = co_base + grp * CG + 2 * j;
        float* op0 = gout + ((long long)img * cout_total + co0) * 81 + y * 9;
        float* op1 = op0 + 81;
        unsigned long long s2 = 0ull, q2 = 0ull;
#pragma unroll
        for (int x = 0; x < 9; x++) {
            unsigned long long v = acc2[j][x];
            float2 f = upk2(v);
            op0[x] = f.x; op1[x] = f.y;
            add2(s2, v); fma2(q2, v, v);
        }
        float2 s = upk2(s2), q = upk2(q2);
        atomicAdd(&red[grp * CG + 2 * j], s.x);
        atomicAdd(&red[grp * CG + 2 * j + 1], s.y);
        atomicAdd(&red[COUT_T + grp * CG + 2 * j], q.x);
        atomicAdd(&red[COUT_T + grp * CG + 2 * j + 1], q.y);
    }
    __syncthreads();
    for (int idx = tid; idx < COUT_T; idx += nthr) {
        atomicAdd(&gsum[co_base + idx], red[idx]);
        atomicAdd(&gsq[co_base + idx], red[COUT_T + idx]);
    }
}

// ---------- BN helpers ----------
__global__ void zero_stats_kernel(float* gsum, float* gsq) {
    int t = threadIdx.x;
    if (t < 384) { gsum[t] = 0.f; gsq[t] = 0.f; }
}
__global__ void bn_prep_kernel(const float* gsum, const float* gsq, const float* gamma,
                               const float* beta, float* a, float* b, int C) {
    int c = threadIdx.x;
    if (c < C) {
        float mu = gsum[c] * INV_CNT;
        float var = gsq[c] * INV_CNT - mu * mu;
        float ai = gamma[c] * rsqrtf(var + BN_EPS);
        a[c] = ai; b[c] = beta[c] - mu * ai;
    }
}

// ---------- conv3 -> bf16 hi/lo pairs with BN+ReLU (slot-permuted) ----------
__global__ void bf16cvt_kernel(const float* __restrict__ x, const float* __restrict__ bnA,
                               const float* __restrict__ bnB, uint32_t* __restrict__ hi,
                               uint32_t* __restrict__ lo) {
    int idx = blockIdx.x * 256 + threadIdx.x;
    if (idx >= NIMG * 5184) return;
    int img = idx / 5184, kp = idx - img * 5184;
    int k0 = kp * 2;
    int ch0 = k0 / 81, ch1 = (k0 + 1) / 81;
    const float* row = x + (long long)img * KDIM;
    float v0 = fmaxf(fmaf(bnA[ch0], row[k0], bnB[ch0]), 0.f);
    float v1 = fmaxf(fmaf(bnA[ch1], row[k0 + 1], bnB[ch1]), 0.f);
    uint32_t h0 = f2bf(v0), h1 = f2bf(v1);
    uint32_t l0 = f2bf(v0 - bf2f(h0)), l1 = f2bf(v1 - bf2f(h1));
    int lp = kp & 7;
    int dst = img * 5184 + (kp & ~7) + (lp & 3) * 2 + (lp >> 2);
    hi[dst] = h0 | (h1 << 16);
    lo[dst] = l0 | (l1 << 16);
}

// ---------- encoder GEMM via mma, split-K=2 ----------
__global__ void __launch_bounds__(256) enc_mma_kernel(
    const uint32_t* __restrict__ bhig, const uint32_t* __restrict__ blog,
    const uint4* __restrict__ afh, const uint4* __restrict__ afl,
    float* __restrict__ part) {
    __shared__ uint32_t Bs[2][2][64][8];
    const int tid = threadIdx.x, wid = tid >> 5, lane = tid & 31;
    const int g = lane >> 2, tg = lane & 3;
    const int m0 = (blockIdx.x & 127) * 64;
    const int ks = blockIdx.x >> 7;
    const int sbase = ks * 324;

    float acc[8][4];
#pragma unroll
    for (int nt = 0; nt < 8; nt++)
#pragma unroll
        for (int i = 0; i < 4; i++) acc[nt][i] = 0.f;

    const int lrow = (tid & 127) >> 1, lhalf = tid & 1, lterm = tid >> 7;
    const uint32_t* lsrc = (lterm == 0 ? bhig : blog) + (size_t)(m0 + lrow) * 5184
                           + sbase * 8 + lhalf * 4;

    *(uint4*)&Bs[0][lterm][lrow][lhalf * 4] = *(const uint4*)(lsrc);
    __syncthreads();

    uint4 Ah = afh[(wid * 648 + sbase) * 32 + lane];
    uint4 Al = afl[(wid * 648 + sbase) * 32 + lane];

    for (int s = 0; s < 324; s++) {
        int st = s & 1;
        if (s + 1 < 324)
            *(uint4*)&Bs[st ^ 1][lterm][lrow][lhalf * 4] = *(const uint4*)(lsrc + (s + 1) * 8);
        uint4 Ah2, Al2;
        if (s + 1 < 324) {
            Ah2 = afh[(wid * 648 + sbase + s + 1) * 32 + lane];
            Al2 = afl[(wid * 648 + sbase + s + 1) * 32 + lane];
        }
#pragma unroll
        for (int nt = 0; nt < 8; nt++) {
            int col = nt * 8 + g;
            uint2 bh = *(const uint2*)&Bs[st][0][col][tg * 2];
            uint2 bl = *(const uint2*)&Bs[st][1][col][tg * 2];
            mma16816(acc[nt], Ah.x, Ah.y, Ah.z, Ah.w, bh.x, bh.y);
            mma16816(acc[nt], Al.x, Al.y, Al.z, Al.w, bh.x, bh.y);
            mma16816(acc[nt], Ah.x, Ah.y, Ah.z, Ah.w, bl.x, bl.y);
        }
        Ah = Ah2; Al = Al2;
        __syncthreads();
    }

    const int e0 = wid * 16 + g, e1 = e0 + 8;
    float* pp = part + ks * (NIMG * ENCF);
#pragma unroll
    for (int nt = 0; nt < 8; nt++) {
        int n = nt * 8 + tg * 2;
        pp[(m0 + n) * ENCF + e0]     = acc[nt][0];
        pp[(m0 + n + 1) * ENCF + e0] = acc[nt][1];
        pp[(m0 + n) * ENCF + e1]     = acc[nt][2];
        pp[(m0 + n + 1) * ENCF + e1] = acc[nt][3];
    }
}

__global__ void combine_enc_kernel(const float* __restrict__ part, const float* __restrict__ enc_b,
                                   float* __restrict__ xcat) {
    int idx = blockIdx.x * 256 + threadIdx.x;
    int e = idx & 127, m = idx >> 7, b = m >> 7, n = m & 127;
    float v = part[idx] + part[NIMG * ENCF + idx] + enc_b[e];
    xcat[b * (384 * 128) + e * 128 + n] = v;
}

// ---------- X*S and X*S^2 (f-rows split across 2 blocks per batch) ----------
__global__ void xs_kernel(float* __restrict__ xcat, const float* __restrict__ gso) {
    extern __shared__ float smf[];
    float (*Xs)[129] = (float (*)[129])smf;
    float (*Ss)[129] = (float (*)[129])(smf + 64 * 129);
    const int b = blockIdx.x >> 1, fh = blockIdx.x & 1;
    const int tx = threadIdx.x;
    for (int l = 0; l < 64; l++) {
        int idx = tx + l * 256, r = idx >> 7, c = idx & 127;
        Ss[r][c] = gso[b * 16384 + idx];
    }
    for (int l = 0; l < 32; l++) {
        int idx = tx + l * 256, r = idx >> 7, c = idx & 127;
        Xs[r][c] = xcat[b * (384 * 128) + (fh * 64 + r) * 128 + c];
    }
    __syncthreads();
    const int nj = tx & 15, fi = tx >> 4;
    unsigned long long acc2[4][4];
    for (int pass = 0; pass < 2; pass++) {
#pragma unroll
        for (int i = 0; i < 4; i++)
#pragma unroll
            for (int j = 0; j < 4; j++) acc2[i][j] = 0ull;
        for (int n = 0; n < 128; n++) {
            unsigned long long sp[4];
#pragma unroll
            for (int j = 0; j < 4; j++) sp[j] = pk2(Ss[n][nj + 32 * j], Ss[n][nj + 16 + 32 * j]);
#pragma unroll
            for (int i = 0; i < 4; i++) {
                unsigned long long xb = bc2(Xs[fi + 16 * i][n]);
#pragma unroll
                for (int j = 0; j < 4; j++) fma2(acc2[i][j], xb, sp[j]);
            }
        }
        __syncthreads();
        float* gdst = xcat + b * (384 * 128) + (pass + 1) * 16384 + fh * 64 * 128;
#pragma unroll
        for (int i = 0; i < 4; i++)
#pragma unroll
            for (int j = 0; j < 4; j++) {
                float2 v = upk2(acc2[i][j]);
                int f = fi + 16 * i;
                Xs[f][nj + 32 * j] = v.x; Xs[f][nj + 16 + 32 * j] = v.y;
                gdst[f * 128 + nj + 32 * j] = v.x;
                gdst[f * 128 + nj + 16 + 32 * j] = v.y;
            }
        __syncthreads();
    }
}

// ---------- graph-filter GEMM (2 blocks per batch) ----------
__global__ void gfilter_kernel(const float* __restrict__ xcat, const float* __restrict__ W,
                               const float* __restrict__ bias, float* __restrict__ out,
                               int out_stride) {
    extern __shared__ float smf[];
    float (*Ws)[97] = (float (*)[97])smf;
    float (*Xs)[129] = (float (*)[129])(smf + 64 * 97);
    const int b = blockIdx.x >> 1, half = blockIdx.x & 1;
    const int tx = threadIdx.x;
    const int nj = tx & 15, gi = tx >> 4;
    unsigned long long acc2[4][4];
#pragma unroll
    for (int i = 0; i < 4; i++)
#pragma unroll
        for (int j = 0; j < 4; j++) acc2[i][j] = 0ull;
    for (int kt = 0; kt < 4; kt++) {
        for (int l = 0; l < 24; l++) {
            int idx = tx + l * 256;
            int g = idx / 96, kc = idx - g * 96;
            int kg = kt * 96 + kc;
            Ws[g][kc] = W[(kg >> 7) * 16384 + (half * 64 + g) * 128 + (kg & 127)];
        }
        for (int l = 0; l < 48; l++) {
            int idx = tx + l * 256, r = idx >> 7, c = idx & 127;
            Xs[r][c] = xcat[b * (384 * 128) + (kt * 96 + r) * 128 + c];
        }
        __syncthreads();
        for (int kc = 0; kc < 96; kc++) {
            unsigned long long xp[4];
#pragma unroll
            for (int j = 0; j < 4; j++) xp[j] = pk2(Xs[kc][nj + 32 * j], Xs[kc][nj + 16 + 32 * j]);
#pragma unroll
            for (int i = 0; i < 4; i++) {
                unsigned long long wb = bc2(Ws[gi + 16 * i][kc]);
#pragma unroll
                for (int j = 0; j < 4; j++) fma2(acc2[i][j], wb, xp[j]);
            }
        }
        __syncthreads();
    }
#pragma unroll
    for (int i = 0; i < 4; i++) {
        int g = half * 64 + gi + 16 * i;
        float bb = bias[g];
#pragma unroll
        for (int j = 0; j < 4; j++) {
            float2 v = upk2(acc2[i][j]);
            out[b * out_stride + g * 128 + nj + 32 * j] = fmaxf(v.x + bb, 0.f);
            out[b * out_stride + g * 128 + nj + 16 + 32 * j] = fmaxf(v.y + bb, 0.f);
        }
    }
}

// ---------- action head ----------
__global__ void act_kernel(const float* __restrict__ xg2, const float* __restrict__ aw,
                           const float* __restrict__ ab, float* __restrict__ out) {
    extern __shared__ float smf[];
    float* xs = smf;
    float* ws = smf + 16384;
    const int b = blockIdx.x, t = threadIdx.x;
    for (int i = t; i < 16384; i += 256) xs[i] = xg2[b * 16384 + i];
    for (int i = t; i < 640; i += 256) ws[i] = aw[i];
    __syncthreads();
    for (int o = t; o < 640; o += 256) {
        int a = o % 5, n = o / 5;
        float s = ab[a];
        const float* wp = ws + a * 128;
        const float* xp = xs + n;
#pragma unroll 8
        for (int g = 0; g < 128; g++) s = fmaf(xp[g * 128], wp[g], s);
        out[b * 640 + o] = s;
    }
}

// ---------- host launcher ----------
extern "C" void kernel_launch(void* const* d_in, const int* in_sizes, int n_in,
                              void* d_out, int out_size) {
    (void)in_sizes; (void)n_in; (void)out_size;
    const float* states = (const float*)d_in[0];
    const float* gso = (const float*)d_in[1];
    const float* c1_w = (const float*)d_in[2];
    const float* c1_g = (const float*)d_in[4];
    const float* c1_be = (const float*)d_in[5];
    const float* c2_w = (const float*)d_in[6];
    const float* c2_g = (const float*)d_in[8];
    const float* c2_be = (const float*)d_in[9];
    const float* c3_w = (const float*)d_in[10];
    const float* c3_g = (const float*)d_in[12];
    const float* c3_be = (const float*)d_in[13];
    const float* enc_w = (const float*)d_in[14];
    const float* enc_b = (const float*)d_in[15];
    const float* g1_w = (const float*)d_in[16];
    const float* g1_b = (const float*)d_in[17];
    const float* g2_w = (const float*)d_in[18];
    const float* g2_b = (const float*)d_in[19];
    const float* act_w = (const float*)d_in[20];
    const float* act_b = (const float*)d_in[21];
    float* out = (float*)d_out;

    void *p1, *p2, *p3, *pp, *px1, *px2, *pg2, *ps, *pq, *pa, *pb;
    void *a2h, *a2l, *a3h, *a3l, *aeh, *ael, *bhi, *blo;
    cudaGetSymbolAddress(&p1, d_conv1);  cudaGetSymbolAddress(&p2, d_conv2);
    cudaGetSymbolAddress(&p3, d_conv3);  cudaGetSymbolAddress(&pp, d_part);
    cudaGetSymbolAddress(&px1, d_xcat1); cudaGetSymbolAddress(&px2, d_xcat2);
    cudaGetSymbolAddress(&pg2, d_xg2);   cudaGetSymbolAddress(&ps, d_gsum);
    cudaGetSymbolAddress(&pq, d_gsq);    cudaGetSymbolAddress(&pa, d_bnA);
    cudaGetSymbolAddress(&pb, d_bnB);
    cudaGetSymbolAddress(&a2h, d_a2h);   cudaGetSymbolAddress(&a2l, d_a2l);
    cudaGetSymbolAddress(&a3h, d_a3h);   cudaGetSymbolAddress(&a3l, d_a3l);
    cudaGetSymbolAddress(&aeh, d_aeh);   cudaGetSymbolAddress(&ael, d_ael);
    cudaGetSymbolAddress(&bhi, d_bhi);   cudaGetSymbolAddress(&blo, d_blo);
    float *conv1 = (float*)p1, *conv2 = (float*)p2, *conv3 = (float*)p3;
    float *part = (float*)pp;
    float *xcat1 = (float*)px1, *xcat2 = (float*)px2, *xg2 = (float*)pg2;
    float *gsum = (float*)ps, *gsq = (float*)pq, *bnA = (float*)pa, *bnB = (float*)pb;

    // conv1 CG=2: TASKS = (32/2)*9 = 144, block (144,2) = 288 threads
    const int SM1 = (32 * 29 + 2 * 3 * 121 + 64) * 4;
    // conv_mma smem: Bs 33792 + pc PL*4 + ofsp (KREAL/2)*4 + pofs 164 + red 2*COUT*4
    const int SMC2 = 33792 + 32 * 121 * 4 + 144 * 4 + 164 + 2 * 64 * 4;    // 50516
    const int SMC3 = 33792 + 64 * 121 * 4 + 288 * 4 + 164 + 2 * 128 * 4;   // 67204
    const int XS_SMEM = (64 * 129 + 128 * 129) * 4;
    const int GF_SMEM = (64 * 97 + 96 * 129) * 4;
    const int ACT_SMEM = (16384 + 640) * 4;

    cudaFuncSetAttribute(conv_bn_stats_kernel<3, 32, 2, 2>, cudaFuncAttributeMaxDynamicSharedMemorySize, SM1);
    cudaFuncSetAttribute(conv_mma_kernel<32, 64, 18, 6, 3>, cudaFuncAttributeMaxDynamicSharedMemorySize, SMC2);
    cudaFuncSetAttribute(conv_mma_kernel<64, 128, 36, 11, 2>, cudaFuncAttributeMaxDynamicSharedMemorySize, SMC3);
    cudaFuncSetAttribute(xs_kernel, cudaFuncAttributeMaxDynamicSharedMemorySize, XS_SMEM);
    cudaFuncSetAttribute(gfilter_kernel, cudaFuncAttributeMaxDynamicSharedMemorySize, GF_SMEM);
    cudaFuncSetAttribute(act_kernel, cudaFuncAttributeMaxDynamicSharedMemorySize, ACT_SMEM);

    zero_stats_kernel<<<1, 384>>>(gsum, gsq);
    prepack_frag_kernel<<<(4 * 18 * 32 + 255) / 256, 256>>>(c2_w, (uint4*)a2h, (uint4*)a2l, 4, 18, 288);
    prepack_frag_kernel<<<(8 * 36 * 32 + 255) / 256, 256>>>(c3_w, (uint4*)a3h, (uint4*)a3l, 8, 36, 576);
    prepack_frag_kernel<<<648, 256>>>(enc_w, (uint4*)aeh, (uint4*)ael, 8, 648, 10368);

    conv_bn_stats_kernel<3, 32, 2, 2>
        <<<dim3(NIMG / 2, 1), dim3(144, 2), SM1>>>(states, c1_w, conv1, gsum, gsq, 32);
    bn_prep_kernel<<<1, 128>>>(gsum, gsq, c1_g, c1_be, bnA, bnB, 32);

    conv_mma_kernel<32, 64, 18, 6, 3><<<444, 256, SMC2>>>(conv1, (const uint4*)a2h, (const uint4*)a2l,
                                                          bnA, bnB, conv2, gsum + 128, gsq + 128);
    bn_prep_kernel<<<1, 128>>>(gsum + 128, gsq + 128, c2_g, c2_be, bnA + 128, bnB + 128, 64);

    conv_mma_kernel<64, 128, 36, 11, 2><<<296, 256, SMC3>>>(conv2, (const uint4*)a3h, (const uint4*)a3l,
                                                            bnA + 128, bnB + 128, conv3,
                                                            gsum + 256, gsq + 256);
    bn_prep_kernel<<<1, 128>>>(gsum + 256, gsq + 256, c3_g, c3_be, bnA + 256, bnB + 256, 128);

    bf16cvt_kernel<<<(NIMG * 5184 + 255) / 256, 256>>>(conv3, bnA + 256, bnB + 256,
                                                       (uint32_t*)bhi, (uint32_t*)blo);
    enc_mma_kernel<<<256, 256>>>((const uint32_t*)bhi, (const uint32_t*)blo,
                                 (const uint4*)aeh, (const uint4*)ael, part);
    combine_enc_kernel<<<4096, 256>>>(part, enc_b, xcat1);

    xs_kernel<<<BATCH * 2, 256, XS_SMEM>>>(xcat1, gso);
    gfilter_kernel<<<BATCH * 2, 256, GF_SMEM>>>(xcat1, g1_w, g1_b, xcat2, 384 * 128);
    xs_kernel<<<BATCH * 2, 256, XS_SMEM>>>(xcat2, gso);
    gfilter_kernel<<<BATCH * 2, 256, GF_SMEM>>>(xcat2, g2_w, g2_b, xg2, 128 * 128);
    act_kernel<<<BATCH, 256, ACT_SMEM>>>(xg2, act_w, act_b, out);
}

// round 13
// speedup vs baseline: 1.0757x; 1.0103x over previous
#include <cuda_runtime.h>
#include <cstdint>

static constexpr int NIMG = 8192;
static constexpr int PIX  = 81;
static constexpr int BATCH = 64;
static constexpr int ENCF = 128;
static constexpr int KDIM = 10368;
static constexpr float BN_EPS = 1e-5f;
static constexpr float INV_CNT = 1.0f / (8192.0f * 81.0f);

__device__ float d_conv1[NIMG * 32 * PIX];
__device__ float d_conv2[NIMG * 64 * PIX];
__device__ float d_conv3[NIMG * 128 * PIX];
__device__ float d_part[2 * NIMG * ENCF];
__device__ float d_xcat1[BATCH * 384 * 128];
__device__ float d_xcat2[BATCH * 384 * 128];
__device__ float d_xg2[BATCH * 128 * 128];
__device__ float d_gsum[384];
__device__ float d_gsq[384];
__device__ float d_bnA[384];
__device__ float d_bnB[384];
__device__ uint4 d_a2h[4 * 18 * 32];
__device__ uint4 d_a2l[4 * 18 * 32];
__device__ uint4 d_a3h[8 * 36 * 32];
__device__ uint4 d_a3l[8 * 36 * 32];
__device__ uint4 d_aeh[8 * 648 * 32];
__device__ uint4 d_ael[8 * 648 * 32];
__device__ uint32_t d_bhi[NIMG * 5184];
__device__ uint32_t d_blo[NIMG * 5184];

// ---------- bf16 bit helpers ----------
__device__ __forceinline__ uint32_t f2bf(float f) {
    uint32_t u = __float_as_uint(f);
    return (u + 0x7FFFu + ((u >> 16) & 1u)) >> 16;
}
__device__ __forceinline__ float bf2f(uint32_t h) { return __uint_as_float(h << 16); }

// ---------- f32x2 helpers ----------
__device__ __forceinline__ unsigned long long pk2(float lo, float hi) {
    unsigned long long r; asm("mov.b64 %0, {%1, %2};" : "=l"(r) : "f"(lo), "f"(hi)); return r;
}
__device__ __forceinline__ unsigned long long bc2(float v) {
    unsigned long long r; asm("mov.b64 %0, {%1, %1};" : "=l"(r) : "f"(v)); return r;
}
__device__ __forceinline__ void fma2(unsigned long long& d, unsigned long long a, unsigned long long b) {
    asm("fma.rn.f32x2 %0, %1, %2, %0;" : "+l"(d) : "l"(a), "l"(b));
}
__device__ __forceinline__ void add2(unsigned long long& d, unsigned long long a) {
    asm("add.rn.f32x2 %0, %0, %1;" : "+l"(d) : "l"(a));
}
__device__ __forceinline__ float2 upk2(unsigned long long v) {
    float lo, hi; asm("mov.b64 {%0, %1}, %2;" : "=f"(lo), "=f"(hi) : "l"(v)); return make_float2(lo, hi);
}

// ---------- warp mma m16n8k16 bf16 ----------
__device__ __forceinline__ void mma16816(float* c, uint32_t a0, uint32_t a1, uint32_t a2,
                                         uint32_t a3, uint32_t b0, uint32_t b1) {
    asm volatile("mma.sync.aligned.m16n8k16.row.col.f32.bf16.bf16.f32 "
                 "{%0,%1,%2,%3}, {%4,%5,%6,%7}, {%8,%9}, {%0,%1,%2,%3};"
                 : "+f"(c[0]), "+f"(c[1]), "+f"(c[2]), "+f"(c[3])
                 : "r"(a0), "r"(a1), "r"(a2), "r"(a3), "r"(b0), "r"(b1));
}

// ---------- prepack weights into mma A-fragment order ----------
__global__ void prepack_frag_kernel(const float* __restrict__ w, uint4* __restrict__ ah,
                                    uint4* __restrict__ al, int CT, int NS, int KREAL) {
    int t = blockIdx.x * 256 + threadIdx.x;
    if (t >= CT * NS * 32) return;
    int lane = t & 31, s = (t >> 5) % NS, ct = t / (NS * 32);
    uint32_t vh[4], vl[4];
#pragma unroll
    for (int i = 0; i < 4; i++) {
        int co = ct * 16 + (lane >> 2) + (i & 1) * 8;
        int k = s * 16 + (lane & 3) * 2 + (i >> 1) * 8;
        float w0 = w[co * KREAL + k], w1 = w[co * KREAL + k + 1];
        uint32_t h0 = f2bf(w0), h1 = f2bf(w1);
        uint32_t l0 = f2bf(w0 - bf2f(h0)), l1 = f2bf(w1 - bf2f(h1));
        vh[i] = h0 | (h1 << 16);
        vl[i] = l0 | (l1 << 16);
    }
    ah[t] = make_uint4(vh[0], vh[1], vh[2], vh[3]);
    al[t] = make_uint4(vl[0], vl[1], vl[2], vl[3]);
}

// ---------- conv via warp mma: packed plane, pad rows pre-zeroed, 2 k-steps/barrier ----------
template <int CIN, int COUT, int NS, int NTMAX, int OCC>
__global__ void __launch_bounds__(256, OCC) conv_mma_kernel(
    const float* __restrict__ gin, const uint4* __restrict__ afh, const uint4* __restrict__ afl,
    const float* __restrict__ bnA, const float* __restrict__ bnB,
    float* __restrict__ gout, float* __restrict__ gsum, float* __restrict__ gsq) {
    constexpr int KREAL = CIN * 9;
    constexpr int CT = COUT / 16;
    constexpr int NS2 = NS / 2;
    constexpr int NROW = 88;
    constexpr int BROW = 12;
    constexpr int BSTG = NROW * BROW;
    constexpr int BSTG2 = 2 * BSTG;
    constexpr int PL = CIN * 121;
    constexpr int OFF_PC   = 2 * 2 * BSTG2 * 4;   // 33792
    constexpr int OFF_OFSP = OFF_PC + PL * 4;
    constexpr int OFF_POF  = OFF_OFSP + (KREAL / 2) * 4;
    constexpr int OFF_RED  = OFF_POF + 81 * 2 + 2;
    extern __shared__ char smc[];
    uint32_t* Bs = (uint32_t*)smc;
    uint32_t* pc   = (uint32_t*)(smc + OFF_PC);
    uint32_t* ofsp = (uint32_t*)(smc + OFF_OFSP);
    unsigned short* pofs = (unsigned short*)(smc + OFF_POF);
    float* red = (float*)(smc + OFF_RED);
    const int tid = threadIdx.x, wid = tid >> 5, lane = tid & 31;
    const int g = lane >> 2, tg = lane & 3;
    const int ct  = (CT == 8) ? wid : (wid & 3);
    const int ntb = (CT == 8) ? 0 : ((wid >> 2) * 6);
    const int ntn = (CT == 8) ? 11 : ((wid >> 2) ? 5 : 6);

    for (int k2 = tid; k2 < KREAL / 2; k2 += 256) {
        int k = 2 * k2;
        int ci0 = k / 9, r0 = k - ci0 * 9;
        int ci1 = (k + 1) / 9, r1 = (k + 1) - ci1 * 9;
        uint32_t o0 = ci0 * 121 + (r0 / 3) * 11 + (r0 % 3);
        uint32_t o1 = ci1 * 121 + (r1 / 3) * 11 + (r1 % 3);
        ofsp[k2] = o0 | (o1 << 16);
    }
    for (int p = tid; p < 81; p += 256) {
        int py = p / 9, px = p - py * 9;
        pofs[p] = (unsigned short)(py * 11 + px);
    }
    for (int i = tid; i < PL; i += 256) pc[i] = 0;
    for (int e = tid; e < 4 * 7 * 16; e += 256) {
        int st4 = e / (7 * 16);
        int rem = e - st4 * 112;
        int p = 81 + rem / 16, kp = rem & 15;
        int sub = kp >> 3, kq = kp & 7;
        Bs[st4 * BSTG2 + sub * BSTG + p * BROW + kq] = 0u;
    }

    float s0 = 0.f, q0 = 0.f, s1 = 0.f, q1 = 0.f;
    const int co0 = ct * 16 + g, co1 = co0 + 8;

    for (int img = blockIdx.x; img < NIMG; img += gridDim.x) {
        __syncthreads();
        const float* ip = gin + (long long)img * (CIN * 81);
        for (int ch = wid; ch < CIN; ch += 8) {
            const float* cp = ip + ch * 81;
            uint32_t* dst = pc + ch * 121;
            float a = bnA[ch], bb = bnB[ch];
            for (int p = lane; p < 81; p += 32) {
                int py = p / 9, px = p - py * 9;
                float v = fmaxf(fmaf(a, cp[p], bb), 0.f);
                uint32_t h = f2bf(v);
                uint32_t l = f2bf(v - bf2f(h));
                dst[(py + 1) * 11 + px + 1] = h | (l << 16);
            }
        }
        __syncthreads();

        float acc[NTMAX][4];
#pragma unroll
        for (int nt = 0; nt < NTMAX; nt++)
#pragma unroll
            for (int i = 0; i < 4; i++) acc[nt][i] = 0.f;

        auto build = [&](int S, int st) {
            uint32_t* bh = Bs + (st * 2 + 0) * BSTG2;
            uint32_t* bl = Bs + (st * 2 + 1) * BSTG2;
            for (int e = tid; e < 81 * 16; e += 256) {
                int p = e >> 4, kp = e & 15;
                uint32_t op = ofsp[S * 16 + kp];
                uint32_t pp = pofs[p];
                uint32_t v0 = pc[(op & 0xFFFFu) + pp];
                uint32_t v1 = pc[(op >> 16) + pp];
                uint32_t bhw = __byte_perm(v0, v1, 0x5410);
                uint32_t blw = __byte_perm(v0, v1, 0x7632);
                int sub = kp >> 3, kq = kp & 7;
                uint32_t off = sub * BSTG + p * BROW + kq;
                bh[off] = bhw;
                bl[off] = blw;
            }
        };

        build(0, 0);
        __syncthreads();

        for (int S = 0; S < NS2; S++) {
            if (S + 1 < NS2) build(S + 1, (S + 1) & 1);
            const uint32_t* cbh = Bs + ((S & 1) * 2 + 0) * BSTG2;
            const uint32_t* cbl = Bs + ((S & 1) * 2 + 1) * BSTG2;
#pragma unroll
            for (int sub = 0; sub < 2; sub++) {
                int s = S * 2 + sub;
                uint4 Ah = afh[(ct * NS + s) * 32 + lane];
                uint4 Al = afl[(ct * NS + s) * 32 + lane];
                const uint32_t* bh = cbh + sub * BSTG;
                const uint32_t* bl = cbl + sub * BSTG;
#pragma unroll
                for (int nt = 0; nt < NTMAX; nt++) {
                    if (nt < ntn) {
                        int row = ((ntb + nt) * 8 + g) * BROW;
                        uint32_t b0 = bh[row + tg], b1 = bh[row + 4 + tg];
                        mma16816(acc[nt], Ah.x, Ah.y, Ah.z, Ah.w, b0, b1);
                        mma16816(acc[nt], Al.x, Al.y, Al.z, Al.w, b0, b1);
                        uint32_t c0 = bl[row + tg], c1 = bl[row + 4 + tg];
                        mma16816(acc[nt], Ah.x, Ah.y, Ah.z, Ah.w, c0, c1);
                    }
                }
            }
            __syncthreads();
        }

        {
            float* op0 = gout + ((long long)img * COUT + co0) * 81;
            float* op1 = gout + ((long long)img * COUT + co1) * 81;
#pragma unroll
            for (int nt = 0; nt < NTMAX; nt++) {
                if (nt < ntn) {
                    int px = (ntb + nt) * 8 + tg * 2;
                    if (px < 81) {
                        op0[px] = acc[nt][0]; s0 += acc[nt][0]; q0 += acc[nt][0] * acc[nt][0];
                        op1[px] = acc[nt][2]; s1 += acc[nt][2]; q1 += acc[nt][2] * acc[nt][2];
                    }
                    if (px + 1 < 81) {
                        op0[px + 1] = acc[nt][1]; s0 += acc[nt][1]; q0 += acc[nt][1] * acc[nt][1];
                        op1[px + 1] = acc[nt][3]; s1 += acc[nt][3]; q1 += acc[nt][3] * acc[nt][3];
                    }
                }
            }
        }
    }

    __syncthreads();
    for (int i = tid; i < 2 * COUT; i += 256) red[i] = 0.f;
    __syncthreads();
    atomicAdd(&red[co0], s0); atomicAdd(&red[COUT + co0], q0);
    atomicAdd(&red[co1], s1); atomicAdd(&red[COUT + co1], q1);
    __syncthreads();
    for (int i = tid; i < COUT; i += 256) {
        atomicAdd(&gsum[i], red[i]);
        atomicAdd(&gsq[i], red[COUT + i]);
    }
}

// ---------- conv1 SIMT (f32x2, fused stats; CG=2) ----------
template <int CIN, int COUT_T, int CG, int IPB>
__global__ void conv_bn_stats_kernel(const float* __restrict__ gin, const float* __restrict__ gw,
                                     float* __restrict__ gout, float* __restrict__ gsum,
                                     float* __restrict__ gsq, int cout_total) {
    constexpr int TASKS = (COUT_T / CG) * 9;
    constexpr int WROW = CIN * 9;
    constexpr int WSTR = (WROW % 2 == 0) ? (WROW + 1) : (WROW + 2);
    constexpr int CG2 = CG / 2;
    extern __shared__ float smf[];
    float* w_s = smf;
    float* in_s = w_s + COUT_T * WSTR;
    float* red = in_s + IPB * CIN * 121;

    const int tx = threadIdx.x, ty = threadIdx.y;
    const int tid = ty * TASKS + tx, nthr = TASKS * IPB;
    const int img = blockIdx.x * IPB + ty;
    const int co_base = blockIdx.y * COUT_T;

    for (int idx = tid; idx < COUT_T * WROW; idx += nthr) {
        int c = idx / WROW, r = idx - c * WROW;
        w_s[c * WSTR + r] = gw[(co_base + c) * WROW + r];
    }
    for (int idx = tid; idx < 2 * COUT_T; idx += nthr) red[idx] = 0.f;
    for (int idx = tid; idx < IPB * CIN * 121; idx += nthr) in_s[idx] = 0.f;
    __syncthreads();
    {
        const float* ip = gin + (long long)img * (CIN * 81);
        float* is = in_s + ty * (CIN * 121);
        for (int idx = tx; idx < CIN * 81; idx += TASKS) {
            int ch = idx / 81, p = idx - ch * 81, y = p / 9, x = p - y * 9;
            is[ch * 121 + (y + 1) * 11 + (x + 1)] = ip[idx];
        }
    }
    __syncthreads();

    const int grp = tx / 9, y = tx - grp * 9;
    unsigned long long acc2[CG2][9];
#pragma unroll
    for (int j = 0; j < CG2; j++)
#pragma unroll
        for (int x = 0; x < 9; x++) acc2[j][x] = 0ull;

    const float* is = in_s + ty * (CIN * 121);
    for (int ci = 0; ci < CIN; ci++) {
        const float* rp = is + ci * 121 + y * 11;
        unsigned long long b0[11], b1[11], b2[11];
#pragma unroll
        for (int x = 0; x < 11; x++) { b0[x] = bc2(rp[x]); b1[x] = bc2(rp[11 + x]); b2[x] = bc2(rp[22 + x]); }
#pragma unroll
        for (int j = 0; j < CG2; j++) {
            const float* wp = w_s + (grp * CG + 2 * j) * WSTR + ci * 9;
            const float* wq = wp + WSTR;
            unsigned long long w[9];
#pragma unroll
            for (int t = 0; t < 9; t++) w[t] = pk2(wp[t], wq[t]);
#pragma unroll
            for (int x = 0; x < 9; x++) {
                fma2(acc2[j][x], b0[x], w[0]); fma2(acc2[j][x], b0[x + 1], w[1]); fma2(acc2[j][x], b0[x + 2], w[2]);
                fma2(acc2[j][x], b1[x], w[3]); fma2(acc2[j][x], b1[x + 1], w[4]); fma2(acc2[j][x], b1[x + 2], w[5]);
                fma2(acc2[j][x], b2[x], w[6]); fma2(acc2[j][x], b2[x + 1], w[7]); fma2(acc2[j][x], b2[x + 2], w[8]);
            }
        }
    }
#pragma unroll
    for (int j = 0; j < CG2; j++) {
        int co0 = co_base + grp * CG + 2 * j;
        float* op0 = gout + ((long long)img * cout_total + co0) * 81 + y * 9;
        float* op1 = op0 + 81;
        unsigned long long s2 = 0ull, q2 = 0ull;
#pragma unroll
        for (int x = 0; x < 9; x++) {
            unsigned long long v = acc2[j][x];
            float2 f = upk2(v);
            op0[x] = f.x; op1[x] = f.y;
            add2(s2, v); fma2(q2, v, v);
        }
        float2 s = upk2(s2), q = upk2(q2);
        atomicAdd(&red[grp * CG + 2 * j], s.x);
        atomicAdd(&red[grp * CG + 2 * j + 1], s.y);
        atomicAdd(&red[COUT_T + grp * CG + 2 * j], q.x);
        atomicAdd(&red[COUT_T + grp * CG + 2 * j + 1], q.y);
    }
    __syncthreads();
    for (int idx = tid; idx < COUT_T; idx += nthr) {
        atomicAdd(&gsum[co_base + idx], red[idx]);
        atomicAdd(&gsq[co_base + idx], red[COUT_T + idx]);
    }
}

// ---------- BN helpers ----------
__global__ void zero_stats_kernel(float* gsum, float* gsq) {
    int t = threadIdx.x;
    if (t < 384) { gsum[t] = 0.f; gsq[t] = 0.f; }
}
__global__ void bn_prep_kernel(const float* gsum, const float* gsq, const float* gamma,
                               const float* beta, float* a, float* b, int C) {
    int c = threadIdx.x;
    if (c < C) {
        float mu = gsum[c] * INV_CNT;
        float var = gsq[c] * INV_CNT - mu * mu;
        float ai = gamma[c] * rsqrtf(var + BN_EPS);
        a[c] = ai; b[c] = beta[c] - mu * ai;
    }
}

// ---------- conv3 -> bf16 hi/lo pairs with BN+ReLU (vectorized, slot-permuted) ----------
__global__ void bf16cvt_kernel(const float* __restrict__ x, const float* __restrict__ bnA,
                               const float* __restrict__ bnB, uint32_t* __restrict__ hi,
                               uint32_t* __restrict__ lo) {
    int idx = blockIdx.x * 256 + threadIdx.x;           // < NIMG * 2592
    if (idx >= NIMG * 2592) return;
    int img = idx / 2592, q = idx - img * 2592;
    int k0 = q * 4;
    float4 v4 = *(const float4*)(x + (long long)img * KDIM + k0);
    float vv[4] = {v4.x, v4.y, v4.z, v4.w};
    uint32_t hw[2], lw[2];
#pragma unroll
    for (int pi = 0; pi < 2; pi++) {
        int ka = k0 + pi * 2;
        int c0 = ka / 81, c1 = (ka + 1) / 81;
        float a0 = fmaxf(fmaf(bnA[c0], vv[pi * 2], bnB[c0]), 0.f);
        float a1 = fmaxf(fmaf(bnA[c1], vv[pi * 2 + 1], bnB[c1]), 0.f);
        uint32_t h0 = f2bf(a0), h1 = f2bf(a1);
        uint32_t l0 = f2bf(a0 - bf2f(h0)), l1 = f2bf(a1 - bf2f(h1));
        hw[pi] = h0 | (h1 << 16);
        lw[pi] = l0 | (l1 << 16);
    }
    int base = img * 5184;
#pragma unroll
    for (int pi = 0; pi < 2; pi++) {
        int kp = q * 2 + pi;
        int lp = kp & 7;
        int dst = base + (kp & ~7) + (lp & 3) * 2 + (lp >> 2);
        hi[dst] = hw[pi];
        lo[dst] = lw[pi];
    }
}

// ---------- encoder GEMM via mma, split-K=2; partials in [ks][e][m] layout ----------
__global__ void __launch_bounds__(256) enc_mma_kernel(
    const uint32_t* __restrict__ bhig, const uint32_t* __restrict__ blog,
    const uint4* __restrict__ afh, const uint4* __restrict__ afl,
    float* __restrict__ part) {
    __shared__ uint32_t Bs[2][2][64][8];
    const int tid = threadIdx.x, wid = tid >> 5, lane = tid & 31;
    const int g = lane >> 2, tg = lane & 3;
    const int m0 = (blockIdx.x & 127) * 64;
    const int ks = blockIdx.x >> 7;
    const int sbase = ks * 324;

    float acc[8][4];
#pragma unroll
    for (int nt = 0; nt < 8; nt++)
#pragma unroll
        for (int i = 0; i < 4; i++) acc[nt][i] = 0.f;

    const int lrow = (tid & 127) >> 1, lhalf = tid & 1, lterm = tid >> 7;
    const uint32_t* lsrc = (lterm == 0 ? bhig : blog) + (size_t)(m0 + lrow) * 5184
                           + sbase * 8 + lhalf * 4;

    *(uint4*)&Bs[0][lterm][lrow][lhalf * 4] = *(const uint4*)(lsrc);
    __syncthreads();

    uint4 Ah = afh[(wid * 648 + sbase) * 32 + lane];
    uint4 Al = afl[(wid * 648 + sbase) * 32 + lane];

    for (int s = 0; s < 324; s++) {
        int st = s & 1;
        if (s + 1 < 324)
            *(uint4*)&Bs[st ^ 1][lterm][lrow][lhalf * 4] = *(const uint4*)(lsrc + (s + 1) * 8);
        uint4 Ah2, Al2;
        if (s + 1 < 324) {
            Ah2 = afh[(wid * 648 + sbase + s + 1) * 32 + lane];
            Al2 = afl[(wid * 648 + sbase + s + 1) * 32 + lane];
        }
#pragma unroll
        for (int nt = 0; nt < 8; nt++) {
            int col = nt * 8 + g;
            uint2 bh = *(const uint2*)&Bs[st][0][col][tg * 2];
            uint2 bl = *(const uint2*)&Bs[st][1][col][tg * 2];
            mma16816(acc[nt], Ah.x, Ah.y, Ah.z, Ah.w, bh.x, bh.y);
            mma16816(acc[nt], Al.x, Al.y, Al.z, Al.w, bh.x, bh.y);
            mma16816(acc[nt], Ah.x, Ah.y, Ah.z, Ah.w, bl.x, bl.y);
        }
        Ah = Ah2; Al = Al2;
        __syncthreads();
    }

    // partial store in [e][m] layout -> quad-contiguous, near-coalesced
    const int e0 = wid * 16 + g, e1 = e0 + 8;
    float* pp = part + ks * (NIMG * ENCF);
#pragma unroll
    for (int nt = 0; nt < 8; nt++) {
        int m = m0 + nt * 8 + tg * 2;
        pp[e0 * NIMG + m]     = acc[nt][0];
        pp[e0 * NIMG + m + 1] = acc[nt][1];
        pp[e1 * NIMG + m]     = acc[nt][2];
        pp[e1 * NIMG + m + 1] = acc[nt][3];
    }
}

// combine split-K partials ([ks][e][m] layout) + bias -> xcat rows [0:128)
__global__ void combine_enc_kernel(const float* __restrict__ part, const float* __restrict__ enc_b,
                                   float* __restrict__ xcat) {
    int idx = blockIdx.x * 256 + threadIdx.x;   // e * 8192 + m
    int e = idx >> 13, m = idx & 8191;
    int b = m >> 7, n = m & 127;
    float v = part[idx] + part[NIMG * ENCF + idx] + enc_b[e];
    xcat[b * (384 * 128) + e * 128 + n] = v;
}

// ---------- X*S and X*S^2 (f-rows split across 2 blocks per batch) ----------
__global__ void xs_kernel(float* __restrict__ xcat, const float* __restrict__ gso) {
    extern __shared__ float smf[];
    float (*Xs)[129] = (float (*)[129])smf;
    float (*Ss)[129] = (float (*)[129])(smf + 64 * 129);
    const int b = blockIdx.x >> 1, fh = blockIdx.x & 1;
    const int tx = threadIdx.x;
    for (int l = 0; l < 64; l++) {
        int idx = tx + l * 256, r = idx >> 7, c = idx & 127;
        Ss[r][c] = gso[b * 16384 + idx];
    }
    for (int l = 0; l < 32; l++) {
        int idx = tx + l * 256, r = idx >> 7, c = idx & 127;
        Xs[r][c] = xcat[b * (384 * 128) + (fh * 64 + r) * 128 + c];
    }
    __syncthreads();
    const int nj = tx & 15, fi = tx >> 4;
    unsigned long long acc2[4][4];
    for (int pass = 0; pass < 2; pass++) {
#pragma unroll
        for (int i = 0; i < 4; i++)
#pragma unroll
            for (int j = 0; j < 4; j++) acc2[i][j] = 0ull;
        for (int n = 0; n < 128; n++) {
            unsigned long long sp[4];
#pragma unroll
            for (int j = 0; j < 4; j++) sp[j] = pk2(Ss[n][nj + 32 * j], Ss[n][nj + 16 + 32 * j]);
#pragma unroll
            for (int i = 0; i < 4; i++) {
                unsigned long long xb = bc2(Xs[fi + 16 * i][n]);
#pragma unroll
                for (int j = 0; j < 4; j++) fma2(acc2[i][j], xb, sp[j]);
            }
        }
        __syncthreads();
        float* gdst = xcat + b * (384 * 128) + (pass + 1) * 16384 + fh * 64 * 128;
#pragma unroll
        for (int i = 0; i < 4; i++)
#pragma unroll
            for (int j = 0; j < 4; j++) {
                float2 v = upk2(acc2[i][j]);
                int f = fi + 16 * i;
                Xs[f][nj + 32 * j] = v.x; Xs[f][nj + 16 + 32 * j] = v.y;
                gdst[f * 128 + nj + 32 * j] = v.x;
                gdst[f * 128 + nj + 16 + 32 * j] = v.y;
            }
        __syncthreads();
    }
}

// ---------- graph-filter GEMM (2 blocks per batch) ----------
__global__ void gfilter_kernel(const float* __restrict__ xcat, const float* __restrict__ W,
                               const float* __restrict__ bias, float* __restrict__ out,
                               int out_stride) {
    extern __shared__ float smf[];
    float (*Ws)[97] = (float (*)[97])smf;
    float (*Xs)[129] = (float (*)[129])(smf + 64 * 97);
    const int b = blockIdx.x >> 1, half = blockIdx.x & 1;
    const int tx = threadIdx.x;
    const int nj = tx & 15, gi = tx >> 4;
    unsigned long long acc2[4][4];
#pragma unroll
    for (int i = 0; i < 4; i++)
#pragma unroll
        for (int j = 0; j < 4; j++) acc2[i][j] = 0ull;
    for (int kt = 0; kt < 4; kt++) {
        for (int l = 0; l < 24; l++) {
            int idx = tx + l * 256;
            int g = idx / 96, kc = idx - g * 96;
            int kg = kt * 96 + kc;
            Ws[g][kc] = W[(kg >> 7) * 16384 + (half * 64 + g) * 128 + (kg & 127)];
        }
        for (int l = 0; l < 48; l++) {
            int idx = tx + l * 256, r = idx >> 7, c = idx & 127;
            Xs[r][c] = xcat[b * (384 * 128) + (kt * 96 + r) * 128 + c];
        }
        __syncthreads();
        for (int kc = 0; kc < 96; kc++) {
            unsigned long long xp[4];
#pragma unroll
            for (int j = 0; j < 4; j++) xp[j] = pk2(Xs[kc][nj + 32 * j], Xs[kc][nj + 16 + 32 * j]);
#pragma unroll
            for (int i = 0; i < 4; i++) {
                unsigned long long wb = bc2(Ws[gi + 16 * i][kc]);
#pragma unroll
                for (int j = 0; j < 4; j++) fma2(acc2[i][j], wb, xp[j]);
            }
        }
        __syncthreads();
    }
#pragma unroll
    for (int i = 0; i < 4; i++) {
        int g = half * 64 + gi + 16 * i;
        float bb = bias[g];
#pragma unroll
        for (int j = 0; j < 4; j++) {
            float2 v = upk2(acc2[i][j]);
            out[b * out_stride + g * 128 + nj + 32 * j] = fmaxf(v.x + bb, 0.f);
            out[b * out_stride + g * 128 + nj + 16 + 32 * j] = fmaxf(v.y + bb, 0.f);
        }
    }
}

// ---------- action head ----------
__global__ void act_kernel(const float* __restrict__ xg2, const float* __restrict__ aw,
                           const float* __restrict__ ab, float* __restrict__ out) {
    extern __shared__ float smf[];
    float* xs = smf;
    float* ws = smf + 16384;
    const int b = blockIdx.x, t = threadIdx.x;
    for (int i = t; i < 16384; i += 256) xs[i] = xg2[b * 16384 + i];
    for (int i = t; i < 640; i += 256) ws[i] = aw[i];
    __syncthreads();
    for (int o = t; o < 640; o += 256) {
        int a = o % 5, n = o / 5;
        float s = ab[a];
        const float* wp = ws + a * 128;
        const float* xp = xs + n;
#pragma unroll 8
        for (int g = 0; g < 128; g++) s = fmaf(xp[g * 128], wp[g], s);
        out[b * 640 + o] = s;
    }
}

// ---------- host launcher ----------
extern "C" void kernel_launch(void* const* d_in, const int* in_sizes, int n_in,
                              void* d_out, int out_size) {
    (void)in_sizes; (void)n_in; (void)out_size;
    const float* states = (const float*)d_in[0];
    const float* gso = (const float*)d_in[1];
    const float* c1_w = (const float*)d_in[2];
    const float* c1_g = (const float*)d_in[4];
    const float* c1_be = (const float*)d_in[5];
    const float* c2_w = (const float*)d_in[6];
    const float* c2_g = (const float*)d_in[8];
    const float* c2_be = (const float*)d_in[9];
    const float* c3_w = (const float*)d_in[10];
    const float* c3_g = (const float*)d_in[12];
    const float* c3_be = (const float*)d_in[13];
    const float* enc_w = (const float*)d_in[14];
    const float* enc_b = (const float*)d_in[15];
    const float* g1_w = (const float*)d_in[16];
    const float* g1_b = (const float*)d_in[17];
    const float* g2_w = (const float*)d_in[18];
    const float* g2_b = (const float*)d_in[19];
    const float* act_w = (const float*)d_in[20];
    const float* act_b = (const float*)d_in[21];
    float* out = (float*)d_out;

    void *p1, *p2, *p3, *pp, *px1, *px2, *pg2, *ps, *pq, *pa, *pb;
    void *a2h, *a2l, *a3h, *a3l, *aeh, *ael, *bhi, *blo;
    cudaGetSymbolAddress(&p1, d_conv1);  cudaGetSymbolAddress(&p2, d_conv2);
    cudaGetSymbolAddress(&p3, d_conv3);  cudaGetSymbolAddress(&pp, d_part);
    cudaGetSymbolAddress(&px1, d_xcat1); cudaGetSymbolAddress(&px2, d_xcat2);
    cudaGetSymbolAddress(&pg2, d_xg2);   cudaGetSymbolAddress(&ps, d_gsum);
    cudaGetSymbolAddress(&pq, d_gsq);    cudaGetSymbolAddress(&pa, d_bnA);
    cudaGetSymbolAddress(&pb, d_bnB);
    cudaGetSymbolAddress(&a2h, d_a2h);   cudaGetSymbolAddress(&a2l, d_a2l);
    cudaGetSymbolAddress(&a3h, d_a3h);   cudaGetSymbolAddress(&a3l, d_a3l);
    cudaGetSymbolAddress(&aeh, d_aeh);   cudaGetSymbolAddress(&ael, d_ael);
    cudaGetSymbolAddress(&bhi, d_bhi);   cudaGetSymbolAddress(&blo, d_blo);
    float *conv1 = (float*)p1, *conv2 = (float*)p2, *conv3 = (float*)p3;
    float *part = (float*)pp;
    float *xcat1 = (float*)px1, *xcat2 = (float*)px2, *xg2 = (float*)pg2;
    float *gsum = (float*)ps, *gsq = (float*)pq, *bnA = (float*)pa, *bnB = (float*)pb;

    const int SM1 = (32 * 29 + 2 * 3 * 121 + 64) * 4;
    const int SMC2 = 33792 + 32 * 121 * 4 + 144 * 4 + 164 + 2 * 64 * 4;    // 50516
    const int SMC3 = 33792 + 64 * 121 * 4 + 288 * 4 + 164 + 2 * 128 * 4;   // 67204
    const int XS_SMEM = (64 * 129 + 128 * 129) * 4;
    const int GF_SMEM = (64 * 97 + 96 * 129) * 4;
    const int ACT_SMEM = (16384 + 640) * 4;

    cudaFuncSetAttribute(conv_bn_stats_kernel<3, 32, 2, 2>, cudaFuncAttributeMaxDynamicSharedMemorySize, SM1);
    cudaFuncSetAttribute(conv_mma_kernel<32, 64, 18, 6, 3>, cudaFuncAttributeMaxDynamicSharedMemorySize, SMC2);
    cudaFuncSetAttribute(conv_mma_kernel<64, 128, 36, 11, 2>, cudaFuncAttributeMaxDynamicSharedMemorySize, SMC3);
    cudaFuncSetAttribute(xs_kernel, cudaFuncAttributeMaxDynamicSharedMemorySize, XS_SMEM);
    cudaFuncSetAttribute(gfilter_kernel, cudaFuncAttributeMaxDynamicSharedMemorySize, GF_SMEM);
    cudaFuncSetAttribute(act_kernel, cudaFuncAttributeMaxDynamicSharedMemorySize, ACT_SMEM);

    zero_stats_kernel<<<1, 384>>>(gsum, gsq);
    prepack_frag_kernel<<<(4 * 18 * 32 + 255) / 256, 256>>>(c2_w, (uint4*)a2h, (uint4*)a2l, 4, 18, 288);
    prepack_frag_kernel<<<(8 * 36 * 32 + 255) / 256, 256>>>(c3_w, (uint4*)a3h, (uint4*)a3l, 8, 36, 576);
    prepack_frag_kernel<<<648, 256>>>(enc_w, (uint4*)aeh, (uint4*)ael, 8, 648, 10368);

    conv_bn_stats_kernel<3, 32, 2, 2>
        <<<dim3(NIMG / 2, 1), dim3(144, 2), SM1>>>(states, c1_w, conv1, gsum, gsq, 32);
    bn_prep_kernel<<<1, 128>>>(gsum, gsq, c1_g, c1_be, bnA, bnB, 32);

    conv_mma_kernel<32, 64, 18, 6, 3><<<444, 256, SMC2>>>(conv1, (const uint4*)a2h, (const uint4*)a2l,
                                                          bnA, bnB, conv2, gsum + 128, gsq + 128);
    bn_prep_kernel<<<1, 128>>>(gsum + 128, gsq + 128, c2_g, c2_be, bnA + 128, bnB + 128, 64);

    conv_mma_kernel<64, 128, 36, 11, 2><<<296, 256, SMC3>>>(conv2, (const uint4*)a3h, (const uint4*)a3l,
                                                            bnA + 128, bnB + 128, conv3,
                                                            gsum + 256, gsq + 256);
    bn_prep_kernel<<<1, 128>>>(gsum + 256, gsq + 256, c3_g, c3_be, bnA + 256, bnB + 256, 128);

    bf16cvt_kernel<<<(NIMG * 2592 + 255) / 256, 256>>>(conv3, bnA + 256, bnB + 256,
                                                       (uint32_t*)bhi, (uint32_t*)blo);
    enc_mma_kernel<<<256, 256>>>((const uint32_t*)bhi, (const uint32_t*)blo,
                                 (const uint4*)aeh, (const uint4*)ael, part);
    combine_enc_kernel<<<4096, 256>>>(part, enc_b, xcat1);

    xs_kernel<<<BATCH * 2, 256, XS_SMEM>>>(xcat1, gso);
    gfilter_kernel<<<BATCH * 2, 256, GF_SMEM>>>(xcat1, g1_w, g1_b, xcat2, 384 * 128);
    xs_kernel<<<BATCH * 2, 256, XS_SMEM>>>(xcat2, gso);
    gfilter_kernel<<<BATCH * 2, 256, GF_SMEM>>>(xcat2, g2_w, g2_b, xg2, 128 * 128);
    act_kernel<<<BATCH, 256, ACT_SMEM>>>(xg2, act_w, act_b, out);
}

// round 14
// speedup vs baseline: 1.1194x; 1.0406x over previous
#include <cuda_runtime.h>
#include <cstdint>

static constexpr int NIMG = 8192;
static constexpr int PIX  = 81;
static constexpr int BATCH = 64;
static constexpr int ENCF = 128;
static constexpr int KDIM = 10368;
static constexpr float BN_EPS = 1e-5f;
static constexpr float INV_CNT = 1.0f / (8192.0f * 81.0f);

__device__ float d_conv1[NIMG * 32 * PIX];
__device__ float d_conv2[NIMG * 64 * PIX];
__device__ float d_conv3[NIMG * 128 * PIX];
__device__ float d_part[2 * NIMG * ENCF];
__device__ float d_xcat1[BATCH * 384 * 128];
__device__ float d_xcat2[BATCH * 384 * 128];
__device__ float d_xg2[BATCH * 128 * 128];
__device__ float d_gsum[384];
__device__ float d_gsq[384];
__device__ float d_bnA[384];
__device__ float d_bnB[384];
__device__ uint4 d_a2h[4 * 18 * 32];
__device__ uint4 d_a2l[4 * 18 * 32];
__device__ uint4 d_a3h[8 * 36 * 32];
__device__ uint4 d_a3l[8 * 36 * 32];
__device__ uint4 d_aeh[8 * 648 * 32];
__device__ uint4 d_ael[8 * 648 * 32];
__device__ uint32_t d_bhi[NIMG * 5184];
__device__ uint32_t d_blo[NIMG * 5184];

// ---------- bf16 bit helpers ----------
__device__ __forceinline__ uint32_t f2bf(float f) {
    uint32_t u = __float_as_uint(f);
    return (u + 0x7FFFu + ((u >> 16) & 1u)) >> 16;
}
__device__ __forceinline__ float bf2f(uint32_t h) { return __uint_as_float(h << 16); }

// ---------- f32x2 helpers ----------
__device__ __forceinline__ unsigned long long pk2(float lo, float hi) {
    unsigned long long r; asm("mov.b64 %0, {%1, %2};" : "=l"(r) : "f"(lo), "f"(hi)); return r;
}
__device__ __forceinline__ unsigned long long bc2(float v) {
    unsigned long long r; asm("mov.b64 %0, {%1, %1};" : "=l"(r) : "f"(v)); return r;
}
__device__ __forceinline__ void fma2(unsigned long long& d, unsigned long long a, unsigned long long b) {
    asm("fma.rn.f32x2 %0, %1, %2, %0;" : "+l"(d) : "l"(a), "l"(b));
}
__device__ __forceinline__ void add2(unsigned long long& d, unsigned long long a) {
    asm("add.rn.f32x2 %0, %0, %1;" : "+l"(d) : "l"(a));
}
__device__ __forceinline__ float2 upk2(unsigned long long v) {
    float lo, hi; asm("mov.b64 {%0, %1}, %2;" : "=f"(lo), "=f"(hi) : "l"(v)); return make_float2(lo, hi);
}

// ---------- warp mma m16n8k16 bf16 ----------
__device__ __forceinline__ void mma16816(float* c, uint32_t a0, uint32_t a1, uint32_t a2,
                                         uint32_t a3, uint32_t b0, uint32_t b1) {
    asm volatile("mma.sync.aligned.m16n8k16.row.col.f32.bf16.bf16.f32 "
                 "{%0,%1,%2,%3}, {%4,%5,%6,%7}, {%8,%9}, {%0,%1,%2,%3};"
                 : "+f"(c[0]), "+f"(c[1]), "+f"(c[2]), "+f"(c[3])
                 : "r"(a0), "r"(a1), "r"(a2), "r"(a3), "r"(b0), "r"(b1));
}

// ---------- prepack weights into mma A-fragment order ----------
__global__ void prepack_frag_kernel(const float* __restrict__ w, uint4* __restrict__ ah,
                                    uint4* __restrict__ al, int CT, int NS, int KREAL) {
    int t = blockIdx.x * 256 + threadIdx.x;
    if (t >= CT * NS * 32) return;
    int lane = t & 31, s = (t >> 5) % NS, ct = t / (NS * 32);
    uint32_t vh[4], vl[4];
#pragma unroll
    for (int i = 0; i < 4; i++) {
        int co = ct * 16 + (lane >> 2) + (i & 1) * 8;
        int k = s * 16 + (lane & 3) * 2 + (i >> 1) * 8;
        float w0 = w[co * KREAL + k], w1 = w[co * KREAL + k + 1];
        uint32_t h0 = f2bf(w0), h1 = f2bf(w1);
        uint32_t l0 = f2bf(w0 - bf2f(h0)), l1 = f2bf(w1 - bf2f(h1));
        vh[i] = h0 | (h1 << 16);
        vl[i] = l0 | (l1 << 16);
    }
    ah[t] = make_uint4(vh[0], vh[1], vh[2], vh[3]);
    al[t] = make_uint4(vl[0], vl[1], vl[2], vl[3]);
}

// ---------- conv via warp mma: packed plane, pad rows pre-zeroed, 2 k-steps/barrier ----------
template <int CIN, int COUT, int NS, int NTMAX, int OCC>
__global__ void __launch_bounds__(256, OCC) conv_mma_kernel(
    const float* __restrict__ gin, const uint4* __restrict__ afh, const uint4* __restrict__ afl,
    const float* __restrict__ bnA, const float* __restrict__ bnB,
    float* __restrict__ gout, float* __restrict__ gsum, float* __restrict__ gsq) {
    constexpr int KREAL = CIN * 9;
    constexpr int CT = COUT / 16;
    constexpr int NS2 = NS / 2;
    constexpr int NROW = 88;
    constexpr int BROW = 12;
    constexpr int BSTG = NROW * BROW;
    constexpr int BSTG2 = 2 * BSTG;
    constexpr int PL = CIN * 121;
    constexpr int OFF_PC   = 2 * 2 * BSTG2 * 4;   // 33792
    constexpr int OFF_OFSP = OFF_PC + PL * 4;
    constexpr int OFF_POF  = OFF_OFSP + (KREAL / 2) * 4;
    constexpr int OFF_RED  = OFF_POF + 81 * 2 + 2;
    extern __shared__ char smc[];
    uint32_t* Bs = (uint32_t*)smc;
    uint32_t* pc   = (uint32_t*)(smc + OFF_PC);
    uint32_t* ofsp = (uint32_t*)(smc + OFF_OFSP);
    unsigned short* pofs = (unsigned short*)(smc + OFF_POF);
    float* red = (float*)(smc + OFF_RED);
    const int tid = threadIdx.x, wid = tid >> 5, lane = tid & 31;
    const int g = lane >> 2, tg = lane & 3;
    const int ct  = (CT == 8) ? wid : (wid & 3);
    const int ntb = (CT == 8) ? 0 : ((wid >> 2) * 6);
    const int ntn = (CT == 8) ? 11 : ((wid >> 2) ? 5 : 6);

    for (int k2 = tid; k2 < KREAL / 2; k2 += 256) {
        int k = 2 * k2;
        int ci0 = k / 9, r0 = k - ci0 * 9;
        int ci1 = (k + 1) / 9, r1 = (k + 1) - ci1 * 9;
        uint32_t o0 = ci0 * 121 + (r0 / 3) * 11 + (r0 % 3);
        uint32_t o1 = ci1 * 121 + (r1 / 3) * 11 + (r1 % 3);
        ofsp[k2] = o0 | (o1 << 16);
    }
    for (int p = tid; p < 81; p += 256) {
        int py = p / 9, px = p - py * 9;
        pofs[p] = (unsigned short)(py * 11 + px);
    }
    for (int i = tid; i < PL; i += 256) pc[i] = 0;
    for (int e = tid; e < 4 * 7 * 16; e += 256) {
        int st4 = e / (7 * 16);
        int rem = e - st4 * 112;
        int p = 81 + rem / 16, kp = rem & 15;
        int sub = kp >> 3, kq = kp & 7;
        Bs[st4 * BSTG2 + sub * BSTG + p * BROW + kq] = 0u;
    }

    float s0 = 0.f, q0 = 0.f, s1 = 0.f, q1 = 0.f;
    const int co0 = ct * 16 + g, co1 = co0 + 8;

    for (int img = blockIdx.x; img < NIMG; img += gridDim.x) {
        __syncthreads();
        const float* ip = gin + (long long)img * (CIN * 81);
        for (int ch = wid; ch < CIN; ch += 8) {
            const float* cp = ip + ch * 81;
            uint32_t* dst = pc + ch * 121;
            float a = bnA[ch], bb = bnB[ch];
            for (int p = lane; p < 81; p += 32) {
                int py = p / 9, px = p - py * 9;
                float v = fmaxf(fmaf(a, cp[p], bb), 0.f);
                uint32_t h = f2bf(v);
                uint32_t l = f2bf(v - bf2f(h));
                dst[(py + 1) * 11 + px + 1] = h | (l << 16);
            }
        }
        __syncthreads();

        float acc[NTMAX][4];
#pragma unroll
        for (int nt = 0; nt < NTMAX; nt++)
#pragma unroll
            for (int i = 0; i < 4; i++) acc[nt][i] = 0.f;

        auto build = [&](int S, int st) {
            uint32_t* bh = Bs + (st * 2 + 0) * BSTG2;
            uint32_t* bl = Bs + (st * 2 + 1) * BSTG2;
            for (int e = tid; e < 81 * 16; e += 256) {
                int p = e >> 4, kp = e & 15;
                uint32_t op = ofsp[S * 16 + kp];
                uint32_t pp = pofs[p];
                uint32_t v0 = pc[(op & 0xFFFFu) + pp];
                uint32_t v1 = pc[(op >> 16) + pp];
                uint32_t bhw = __byte_perm(v0, v1, 0x5410);
                uint32_t blw = __byte_perm(v0, v1, 0x7632);
                int sub = kp >> 3, kq = kp & 7;
                uint32_t off = sub * BSTG + p * BROW + kq;
                bh[off] = bhw;
                bl[off] = blw;
            }
        };

        build(0, 0);
        __syncthreads();

        for (int S = 0; S < NS2; S++) {
            if (S + 1 < NS2) build(S + 1, (S + 1) & 1);
            const uint32_t* cbh = Bs + ((S & 1) * 2 + 0) * BSTG2;
            const uint32_t* cbl = Bs + ((S & 1) * 2 + 1) * BSTG2;
#pragma unroll
            for (int sub = 0; sub < 2; sub++) {
                int s = S * 2 + sub;
                uint4 Ah = afh[(ct * NS + s) * 32 + lane];
                uint4 Al = afl[(ct * NS + s) * 32 + lane];
                const uint32_t* bh = cbh + sub * BSTG;
                const uint32_t* bl = cbl + sub * BSTG;
#pragma unroll
                for (int nt = 0; nt < NTMAX; nt++) {
                    if (nt < ntn) {
                        int row = ((ntb + nt) * 8 + g) * BROW;
                        uint32_t b0 = bh[row + tg], b1 = bh[row + 4 + tg];
                        mma16816(acc[nt], Ah.x, Ah.y, Ah.z, Ah.w, b0, b1);
                        mma16816(acc[nt], Al.x, Al.y, Al.z, Al.w, b0, b1);
                        uint32_t c0 = bl[row + tg], c1 = bl[row + 4 + tg];
                        mma16816(acc[nt], Ah.x, Ah.y, Ah.z, Ah.w, c0, c1);
                    }
                }
            }
            __syncthreads();
        }

        {
            float* op0 = gout + ((long long)img * COUT + co0) * 81;
            float* op1 = gout + ((long long)img * COUT + co1) * 81;
#pragma unroll
            for (int nt = 0; nt < NTMAX; nt++) {
                if (nt < ntn) {
                    int px = (ntb + nt) * 8 + tg * 2;
                    if (px < 81) {
                        op0[px] = acc[nt][0]; s0 += acc[nt][0]; q0 += acc[nt][0] * acc[nt][0];
                        op1[px] = acc[nt][2]; s1 += acc[nt][2]; q1 += acc[nt][2] * acc[nt][2];
                    }
                    if (px + 1 < 81) {
                        op0[px + 1] = acc[nt][1]; s0 += acc[nt][1]; q0 += acc[nt][1] * acc[nt][1];
                        op1[px + 1] = acc[nt][3]; s1 += acc[nt][3]; q1 += acc[nt][3] * acc[nt][3];
                    }
                }
            }
        }
    }

    __syncthreads();
    for (int i = tid; i < 2 * COUT; i += 256) red[i] = 0.f;
    __syncthreads();
    atomicAdd(&red[co0], s0); atomicAdd(&red[COUT + co0], q0);
    atomicAdd(&red[co1], s1); atomicAdd(&red[COUT + co1], q1);
    __syncthreads();
    for (int i = tid; i < COUT; i += 256) {
        atomicAdd(&gsum[i], red[i]);
        atomicAdd(&gsq[i], red[COUT + i]);
    }
}

// ---------- conv1 SIMT (f32x2, fused stats; CG=2) ----------
template <int CIN, int COUT_T, int CG, int IPB>
__global__ void conv_bn_stats_kernel(const float* __restrict__ gin, const float* __restrict__ gw,
                                     float* __restrict__ gout, float* __restrict__ gsum,
                                     float* __restrict__ gsq, int cout_total) {
    constexpr int TASKS = (COUT_T / CG) * 9;
    constexpr int WROW = CIN * 9;
    constexpr int WSTR = (WROW % 2 == 0) ? (WROW + 1) : (WROW + 2);
    constexpr int CG2 = CG / 2;
    extern __shared__ float smf[];
    float* w_s = smf;
    float* in_s = w_s + COUT_T * WSTR;
    float* red = in_s + IPB * CIN * 121;

    const int tx = threadIdx.x, ty = threadIdx.y;
    const int tid = ty * TASKS + tx, nthr = TASKS * IPB;
    const int img = blockIdx.x * IPB + ty;
    const int co_base = blockIdx.y * COUT_T;

    for (int idx = tid; idx < COUT_T * WROW; idx += nthr) {
        int c = idx / WROW, r = idx - c * WROW;
        w_s[c * WSTR + r] = gw[(co_base + c) * WROW + r];
    }
    for (int idx = tid; idx < 2 * COUT_T; idx += nthr) red[idx] = 0.f;
    for (int idx = tid; idx < IPB * CIN * 121; idx += nthr) in_s[idx] = 0.f;
    __syncthreads();
    {
        const float* ip = gin + (long long)img * (CIN * 81);
        float* is = in_s + ty * (CIN * 121);
        for (int idx = tx; idx < CIN * 81; idx += TASKS) {
            int ch = idx / 81, p = idx - ch * 81, y = p / 9, x = p - y * 9;
            is[ch * 121 + (y + 1) * 11 + (x + 1)] = ip[idx];
        }
    }
    __syncthreads();

    const int grp = tx / 9, y = tx - grp * 9;
    unsigned long long acc2[CG2][9];
#pragma unroll
    for (int j = 0; j < CG2; j++)
#pragma unroll
        for (int x = 0; x < 9; x++) acc2[j][x] = 0ull;

    const float* is = in_s + ty * (CIN * 121);
    for (int ci = 0; ci < CIN; ci++) {
        const float* rp = is + ci * 121 + y * 11;
        unsigned long long b0[11], b1[11], b2[11];
#pragma unroll
        for (int x = 0; x < 11; x++) { b0[x] = bc2(rp[x]); b1[x] = bc2(rp[11 + x]); b2[x] = bc2(rp[22 + x]); }
#pragma unroll
        for (int j = 0; j < CG2; j++) {
            const float* wp = w_s + (grp * CG + 2 * j) * WSTR + ci * 9;
            const float* wq = wp + WSTR;
            unsigned long long w[9];
#pragma unroll
            for (int t = 0; t < 9; t++) w[t] = pk2(wp[t], wq[t]);
#pragma unroll
            for (int x = 0; x < 9; x++) {
                fma2(acc2[j][x], b0[x], w[0]); fma2(acc2[j][x], b0[x + 1], w[1]); fma2(acc2[j][x], b0[x + 2], w[2]);
                fma2(acc2[j][x], b1[x], w[3]); fma2(acc2[j][x], b1[x + 1], w[4]); fma2(acc2[j][x], b1[x + 2], w[5]);
                fma2(acc2[j][x], b2[x], w[6]); fma2(acc2[j][x], b2[x + 1], w[7]); fma2(acc2[j][x], b2[x + 2], w[8]);
            }
        }
    }
#pragma unroll
    for (int j = 0; j < CG2; j++) {
        int co0 = co_base + grp * CG + 2 * j;
        float* op0 = gout + ((long long)img * cout_total + co0) * 81 + y * 9;
        float* op1 = op0 + 81;
        unsigned long long s2 = 0ull, q2 = 0ull;
#pragma unroll
        for (int x = 0; x < 9; x++) {
            unsigned long long v = acc2[j][x];
            float2 f = upk2(v);
            op0[x] = f.x; op1[x] = f.y;
            add2(s2, v); fma2(q2, v, v);
        }
        float2 s = upk2(s2), q = upk2(q2);
        atomicAdd(&red[grp * CG + 2 * j], s.x);
        atomicAdd(&red[grp * CG + 2 * j + 1], s.y);
        atomicAdd(&red[COUT_T + grp * CG + 2 * j], q.x);
        atomicAdd(&red[COUT_T + grp * CG + 2 * j + 1], q.y);
    }
    __syncthreads();
    for (int idx = tid; idx < COUT_T; idx += nthr) {
        atomicAdd(&gsum[co_base + idx], red[idx]);
        atomicAdd(&gsq[co_base + idx], red[COUT_T + idx]);
    }
}

// ---------- BN helpers ----------
__global__ void zero_stats_kernel(float* gsum, float* gsq) {
    int t = threadIdx.x;
    if (t < 384) { gsum[t] = 0.f; gsq[t] = 0.f; }
}
__global__ void bn_prep_kernel(const float* gsum, const float* gsq, const float* gamma,
                               const float* beta, float* a, float* b, int C) {
    int c = threadIdx.x;
    if (c < C) {
        float mu = gsum[c] * INV_CNT;
        float var = gsq[c] * INV_CNT - mu * mu;
        float ai = gamma[c] * rsqrtf(var + BN_EPS);
        a[c] = ai; b[c] = beta[c] - mu * ai;
    }
}

// ---------- conv3 -> bf16 hi/lo pairs with BN+ReLU (vectorized, slot-permuted) ----------
__global__ void bf16cvt_kernel(const float* __restrict__ x, const float* __restrict__ bnA,
                               const float* __restrict__ bnB, uint32_t* __restrict__ hi,
                               uint32_t* __restrict__ lo) {
    int idx = blockIdx.x * 256 + threadIdx.x;
    if (idx >= NIMG * 2592) return;
    int img = idx / 2592, q = idx - img * 2592;
    int k0 = q * 4;
    float4 v4 = *(const float4*)(x + (long long)img * KDIM + k0);
    float vv[4] = {v4.x, v4.y, v4.z, v4.w};
    uint32_t hw[2], lw[2];
#pragma unroll
    for (int pi = 0; pi < 2; pi++) {
        int ka = k0 + pi * 2;
        int c0 = ka / 81, c1 = (ka + 1) / 81;
        float a0 = fmaxf(fmaf(bnA[c0], vv[pi * 2], bnB[c0]), 0.f);
        float a1 = fmaxf(fmaf(bnA[c1], vv[pi * 2 + 1], bnB[c1]), 0.f);
        uint32_t h0 = f2bf(a0), h1 = f2bf(a1);
        uint32_t l0 = f2bf(a0 - bf2f(h0)), l1 = f2bf(a1 - bf2f(h1));
        hw[pi] = h0 | (h1 << 16);
        lw[pi] = l0 | (l1 << 16);
    }
    int base = img * 5184;
#pragma unroll
    for (int pi = 0; pi < 2; pi++) {
        int kp = q * 2 + pi;
        int lp = kp & 7;
        int dst = base + (kp & ~7) + (lp & 3) * 2 + (lp >> 2);
        hi[dst] = hw[pi];
        lo[dst] = lw[pi];
    }
}

// ---------- encoder GEMM via mma, split-K=2; partials in [ks][e][m] layout ----------
__global__ void __launch_bounds__(256) enc_mma_kernel(
    const uint32_t* __restrict__ bhig, const uint32_t* __restrict__ blog,
    const uint4* __restrict__ afh, const uint4* __restrict__ afl,
    float* __restrict__ part) {
    __shared__ uint32_t Bs[2][2][64][8];
    const int tid = threadIdx.x, wid = tid >> 5, lane = tid & 31;
    const int g = lane >> 2, tg = lane & 3;
    const int m0 = (blockIdx.x & 127) * 64;
    const int ks = blockIdx.x >> 7;
    const int sbase = ks * 324;

    float acc[8][4];
#pragma unroll
    for (int nt = 0; nt < 8; nt++)
#pragma unroll
        for (int i = 0; i < 4; i++) acc[nt][i] = 0.f;

    const int lrow = (tid & 127) >> 1, lhalf = tid & 1, lterm = tid >> 7;
    const uint32_t* lsrc = (lterm == 0 ? bhig : blog) + (size_t)(m0 + lrow) * 5184
                           + sbase * 8 + lhalf * 4;

    *(uint4*)&Bs[0][lterm][lrow][lhalf * 4] = *(const uint4*)(lsrc);
    __syncthreads();

    uint4 Ah = afh[(wid * 648 + sbase) * 32 + lane];
    uint4 Al = afl[(wid * 648 + sbase) * 32 + lane];

    for (int s = 0; s < 324; s++) {
        int st = s & 1;
        if (s + 1 < 324)
            *(uint4*)&Bs[st ^ 1][lterm][lrow][lhalf * 4] = *(const uint4*)(lsrc + (s + 1) * 8);
        uint4 Ah2, Al2;
        if (s + 1 < 324) {
            Ah2 = afh[(wid * 648 + sbase + s + 1) * 32 + lane];
            Al2 = afl[(wid * 648 + sbase + s + 1) * 32 + lane];
        }
#pragma unroll
        for (int nt = 0; nt < 8; nt++) {
            int col = nt * 8 + g;
            uint2 bh = *(const uint2*)&Bs[st][0][col][tg * 2];
            uint2 bl = *(const uint2*)&Bs[st][1][col][tg * 2];
            mma16816(acc[nt], Ah.x, Ah.y, Ah.z, Ah.w, bh.x, bh.y);
            mma16816(acc[nt], Al.x, Al.y, Al.z, Al.w, bh.x, bh.y);
            mma16816(acc[nt], Ah.x, Ah.y, Ah.z, Ah.w, bl.x, bl.y);
        }
        Ah = Ah2; Al = Al2;
        __syncthreads();
    }

    const int e0 = wid * 16 + g, e1 = e0 + 8;
    float* pp = part + ks * (NIMG * ENCF);
#pragma unroll
    for (int nt = 0; nt < 8; nt++) {
        int m = m0 + nt * 8 + tg * 2;
        pp[e0 * NIMG + m]     = acc[nt][0];
        pp[e0 * NIMG + m + 1] = acc[nt][1];
        pp[e1 * NIMG + m]     = acc[nt][2];
        pp[e1 * NIMG + m + 1] = acc[nt][3];
    }
}

__global__ void combine_enc_kernel(const float* __restrict__ part, const float* __restrict__ enc_b,
                                   float* __restrict__ xcat) {
    int idx = blockIdx.x * 256 + threadIdx.x;
    int e = idx >> 13, m = idx & 8191;
    int b = m >> 7, n = m & 127;
    float v = part[idx] + part[NIMG * ENCF + idx] + enc_b[e];
    xcat[b * (384 * 128) + e * 128 + n] = v;
}

// ---------- X*S and X*S^2 (f-rows split across 2 blocks per batch) ----------
__global__ void xs_kernel(float* __restrict__ xcat, const float* __restrict__ gso) {
    extern __shared__ float smf[];
    float (*Xs)[129] = (float (*)[129])smf;
    float (*Ss)[129] = (float (*)[129])(smf + 64 * 129);
    const int b = blockIdx.x >> 1, fh = blockIdx.x & 1;
    const int tx = threadIdx.x;
    for (int l = 0; l < 64; l++) {
        int idx = tx + l * 256, r = idx >> 7, c = idx & 127;
        Ss[r][c] = gso[b * 16384 + idx];
    }
    for (int l = 0; l < 32; l++) {
        int idx = tx + l * 256, r = idx >> 7, c = idx & 127;
        Xs[r][c] = xcat[b * (384 * 128) + (fh * 64 + r) * 128 + c];
    }
    __syncthreads();
    const int nj = tx & 15, fi = tx >> 4;
    unsigned long long acc2[4][4];
    for (int pass = 0; pass < 2; pass++) {
#pragma unroll
        for (int i = 0; i < 4; i++)
#pragma unroll
            for (int j = 0; j < 4; j++) acc2[i][j] = 0ull;
        for (int n = 0; n < 128; n++) {
            unsigned long long sp[4];
#pragma unroll
            for (int j = 0; j < 4; j++) sp[j] = pk2(Ss[n][nj + 32 * j], Ss[n][nj + 16 + 32 * j]);
#pragma unroll
            for (int i = 0; i < 4; i++) {
                unsigned long long xb = bc2(Xs[fi + 16 * i][n]);
#pragma unroll
                for (int j = 0; j < 4; j++) fma2(acc2[i][j], xb, sp[j]);
            }
        }
        __syncthreads();
        float* gdst = xcat + b * (384 * 128) + (pass + 1) * 16384 + fh * 64 * 128;
#pragma unroll
        for (int i = 0; i < 4; i++)
#pragma unroll
            for (int j = 0; j < 4; j++) {
                float2 v = upk2(acc2[i][j]);
                int f = fi + 16 * i;
                Xs[f][nj + 32 * j] = v.x; Xs[f][nj + 16 + 32 * j] = v.y;
                gdst[f * 128 + nj + 32 * j] = v.x;
                gdst[f * 128 + nj + 16 + 32 * j] = v.y;
            }
        __syncthreads();
    }
}

// ---------- graph-filter GEMM (2 blocks per batch) ----------
__global__ void gfilter_kernel(const float* __restrict__ xcat, const float* __restrict__ W,
                               const float* __restrict__ bias, float* __restrict__ out,
                               int out_stride) {
    extern __shared__ float smf[];
    float (*Ws)[97] = (float (*)[97])smf;
    float (*Xs)[129] = (float (*)[129])(smf + 64 * 97);
    const int b = blockIdx.x >> 1, half = blockIdx.x & 1;
    const int tx = threadIdx.x;
    const int nj = tx & 15, gi = tx >> 4;
    unsigned long long acc2[4][4];
#pragma unroll
    for (int i = 0; i < 4; i++)
#pragma unroll
        for (int j = 0; j < 4; j++) acc2[i][j] = 0ull;
    for (int kt = 0; kt < 4; kt++) {
        for (int l = 0; l < 24; l++) {
            int idx = tx + l * 256;
            int g = idx / 96, kc = idx - g * 96;
            int kg = kt * 96 + kc;
            Ws[g][kc] = W[(kg >> 7) * 16384 + (half * 64 + g) * 128 + (kg & 127)];
        }
        for (int l = 0; l < 48; l++) {
            int idx = tx + l * 256, r = idx >> 7, c = idx & 127;
            Xs[r][c] = xcat[b * (384 * 128) + (kt * 96 + r) * 128 + c];
        }
        __syncthreads();
        for (int kc = 0; kc < 96; kc++) {
            unsigned long long xp[4];
#pragma unroll
            for (int j = 0; j < 4; j++) xp[j] = pk2(Xs[kc][nj + 32 * j], Xs[kc][nj + 16 + 32 * j]);
#pragma unroll
            for (int i = 0; i < 4; i++) {
                unsigned long long wb = bc2(Ws[gi + 16 * i][kc]);
#pragma unroll
                for (int j = 0; j < 4; j++) fma2(acc2[i][j], wb, xp[j]);
            }
        }
        __syncthreads();
    }
#pragma unroll
    for (int i = 0; i < 4; i++) {
        int g = half * 64 + gi + 16 * i;
        float bb = bias[g];
#pragma unroll
        for (int j = 0; j < 4; j++) {
            float2 v = upk2(acc2[i][j]);
            out[b * out_stride + g * 128 + nj + 32 * j] = fmaxf(v.x + bb, 0.f);
            out[b * out_stride + g * 128 + nj + 16 + 32 * j] = fmaxf(v.y + bb, 0.f);
        }
    }
}

// ---------- action head ----------
__global__ void act_kernel(const float* __restrict__ xg2, const float* __restrict__ aw,
                           const float* __restrict__ ab, float* __restrict__ out) {
    extern __shared__ float smf[];
    float* xs = smf;
    float* ws = smf + 16384;
    const int b = blockIdx.x, t = threadIdx.x;
    for (int i = t; i < 16384; i += 256) xs[i] = xg2[b * 16384 + i];
    for (int i = t; i < 640; i += 256) ws[i] = aw[i];
    __syncthreads();
    for (int o = t; o < 640; o += 256) {
        int a = o % 5, n = o / 5;
        float s = ab[a];
        const float* wp = ws + a * 128;
        const float* xp = xs + n;
#pragma unroll 8
        for (int g = 0; g < 128; g++) s = fmaf(xp[g * 128], wp[g], s);
        out[b * 640 + o] = s;
    }
}

// ---------- host launcher ----------
extern "C" void kernel_launch(void* const* d_in, const int* in_sizes, int n_in,
                              void* d_out, int out_size) {
    (void)in_sizes; (void)n_in; (void)out_size;
    const float* states = (const float*)d_in[0];
    const float* gso = (const float*)d_in[1];
    const float* c1_w = (const float*)d_in[2];
    const float* c1_g = (const float*)d_in[4];
    const float* c1_be = (const float*)d_in[5];
    const float* c2_w = (const float*)d_in[6];
    const float* c2_g = (const float*)d_in[8];
    const float* c2_be = (const float*)d_in[9];
    const float* c3_w = (const float*)d_in[10];
    const float* c3_g = (const float*)d_in[12];
    const float* c3_be = (const float*)d_in[13];
    const float* enc_w = (const float*)d_in[14];
    const float* enc_b = (const float*)d_in[15];
    const float* g1_w = (const float*)d_in[16];
    const float* g1_b = (const float*)d_in[17];
    const float* g2_w = (const float*)d_in[18];
    const float* g2_b = (const float*)d_in[19];
    const float* act_w = (const float*)d_in[20];
    const float* act_b = (const float*)d_in[21];
    float* out = (float*)d_out;

    void *p1, *p2, *p3, *pp, *px1, *px2, *pg2, *ps, *pq, *pa, *pb;
    void *a2h, *a2l, *a3h, *a3l, *aeh, *ael, *bhi, *blo;
    cudaGetSymbolAddress(&p1, d_conv1);  cudaGetSymbolAddress(&p2, d_conv2);
    cudaGetSymbolAddress(&p3, d_conv3);  cudaGetSymbolAddress(&pp, d_part);
    cudaGetSymbolAddress(&px1, d_xcat1); cudaGetSymbolAddress(&px2, d_xcat2);
    cudaGetSymbolAddress(&pg2, d_xg2);   cudaGetSymbolAddress(&ps, d_gsum);
    cudaGetSymbolAddress(&pq, d_gsq);    cudaGetSymbolAddress(&pa, d_bnA);
    cudaGetSymbolAddress(&pb, d_bnB);
    cudaGetSymbolAddress(&a2h, d_a2h);   cudaGetSymbolAddress(&a2l, d_a2l);
    cudaGetSymbolAddress(&a3h, d_a3h);   cudaGetSymbolAddress(&a3l, d_a3l);
    cudaGetSymbolAddress(&aeh, d_aeh);   cudaGetSymbolAddress(&ael, d_ael);
    cudaGetSymbolAddress(&bhi, d_bhi);   cudaGetSymbolAddress(&blo, d_blo);
    float *conv1 = (float*)p1, *conv2 = (float*)p2, *conv3 = (float*)p3;
    float *part = (float*)pp;
    float *xcat1 = (float*)px1, *xcat2 = (float*)px2, *xg2 = (float*)pg2;
    float *gsum = (float*)ps, *gsq = (float*)pq, *bnA = (float*)pa, *bnB = (float*)pb;

    const int SM1 = (32 * 29 + 2 * 3 * 121 + 64) * 4;
    const int SMC2 = 33792 + 32 * 121 * 4 + 144 * 4 + 164 + 2 * 64 * 4;    // 50516
    const int SMC3 = 33792 + 64 * 121 * 4 + 288 * 4 + 164 + 2 * 128 * 4;   // 67204
    const int XS_SMEM = (64 * 129 + 128 * 129) * 4;
    const int GF_SMEM = (64 * 97 + 96 * 129) * 4;
    const int ACT_SMEM = (16384 + 640) * 4;

    cudaFuncSetAttribute(conv_bn_stats_kernel<3, 32, 2, 2>, cudaFuncAttributeMaxDynamicSharedMemorySize, SM1);
    cudaFuncSetAttribute(conv_mma_kernel<32, 64, 18, 6, 3>, cudaFuncAttributeMaxDynamicSharedMemorySize, SMC2);
    cudaFuncSetAttribute(conv_mma_kernel<64, 128, 36, 11, 3>, cudaFuncAttributeMaxDynamicSharedMemorySize, SMC3);
    cudaFuncSetAttribute(xs_kernel, cudaFuncAttributeMaxDynamicSharedMemorySize, XS_SMEM);
    cudaFuncSetAttribute(gfilter_kernel, cudaFuncAttributeMaxDynamicSharedMemorySize, GF_SMEM);
    cudaFuncSetAttribute(act_kernel, cudaFuncAttributeMaxDynamicSharedMemorySize, ACT_SMEM);

    zero_stats_kernel<<<1, 384>>>(gsum, gsq);
    prepack_frag_kernel<<<(4 * 18 * 32 + 255) / 256, 256>>>(c2_w, (uint4*)a2h, (uint4*)a2l, 4, 18, 288);
    prepack_frag_kernel<<<(8 * 36 * 32 + 255) / 256, 256>>>(c3_w, (uint4*)a3h, (uint4*)a3l, 8, 36, 576);
    prepack_frag_kernel<<<648, 256>>>(enc_w, (uint4*)aeh, (uint4*)ael, 8, 648, 10368);

    conv_bn_stats_kernel<3, 32, 2, 2>
        <<<dim3(NIMG / 2, 1), dim3(144, 2), SM1>>>(states, c1_w, conv1, gsum, gsq, 32);
    bn_prep_kernel<<<1, 128>>>(gsum, gsq, c1_g, c1_be, bnA, bnB, 32);

    conv_mma_kernel<32, 64, 18, 6, 3><<<444, 256, SMC2>>>(conv1, (const uint4*)a2h, (const uint4*)a2l,
                                                          bnA, bnB, conv2, gsum + 128, gsq + 128);
    bn_prep_kernel<<<1, 128>>>(gsum + 128, gsq + 128, c2_g, c2_be, bnA + 128, bnB + 128, 64);

    conv_mma_kernel<64, 128, 36, 11, 3><<<444, 256, SMC3>>>(conv2, (const uint4*)a3h, (const uint4*)a3l,
                                                            bnA + 128, bnB + 128, conv3,
                                                            gsum + 256, gsq + 256);
    bn_prep_kernel<<<1, 128>>>(gsum + 256, gsq + 256, c3_g, c3_be, bnA + 256, bnB + 256, 128);

    bf16cvt_kernel<<<(NIMG * 2592 + 255) / 256, 256>>>(conv3, bnA + 256, bnB + 256,
                                                       (uint32_t*)bhi, (uint32_t*)blo);
    enc_mma_kernel<<<256, 256>>>((const uint32_t*)bhi, (const uint32_t*)blo,
                                 (const uint4*)aeh, (const uint4*)ael, part);
    combine_enc_kernel<<<4096, 256>>>(part, enc_b, xcat1);

    xs_kernel<<<BATCH * 2, 256, XS_SMEM>>>(xcat1, gso);
    gfilter_kernel<<<BATCH * 2, 256, GF_SMEM>>>(xcat1, g1_w, g1_b, xcat2, 384 * 128);
    xs_kernel<<<BATCH * 2, 256, XS_SMEM>>>(xcat2, gso);
    gfilter_kernel<<<BATCH * 2, 256, GF_SMEM>>>(xcat2, g2_w, g2_b, xg2, 128 * 128);
    act_kernel<<<BATCH, 256, ACT_SMEM>>>(xg2, act_w, act_b, out);
}

// round 15
// speedup vs baseline: 1.1208x; 1.0013x over previous
#include <cuda_runtime.h>
#include <cstdint>

static constexpr int NIMG = 8192;
static constexpr int PIX  = 81;
static constexpr int BATCH = 64;
static constexpr int ENCF = 128;
static constexpr int KDIM = 10368;
static constexpr float BN_EPS = 1e-5f;
static constexpr float INV_CNT = 1.0f / (8192.0f * 81.0f);

__device__ float d_conv1[NIMG * 32 * PIX];
__device__ float d_conv2[NIMG * 64 * PIX];
__device__ float d_conv3[NIMG * 128 * PIX];
__device__ float d_part[2 * NIMG * ENCF];
__device__ float d_xcat1[BATCH * 384 * 128];
__device__ float d_xcat2[BATCH * 384 * 128];
__device__ float d_xg2[BATCH * 128 * 128];
__device__ float d_gsum[384];
__device__ float d_gsq[384];
__device__ float d_bnA[384];
__device__ float d_bnB[384];
__device__ uint4 d_a2h[4 * 18 * 32];
__device__ uint4 d_a2l[4 * 18 * 32];
__device__ uint4 d_a3h[8 * 36 * 32];
__device__ uint4 d_a3l[8 * 36 * 32];
__device__ uint4 d_aeh[8 * 648 * 32];
__device__ uint4 d_ael[8 * 648 * 32];
__device__ uint32_t d_bhi[NIMG * 5184];
__device__ uint32_t d_blo[NIMG * 5184];

// ---------- bf16 bit helpers ----------
__device__ __forceinline__ uint32_t f2bf(float f) {
    uint32_t u = __float_as_uint(f);
    return (u + 0x7FFFu + ((u >> 16) & 1u)) >> 16;
}
__device__ __forceinline__ float bf2f(uint32_t h) { return __uint_as_float(h << 16); }

// ---------- f32x2 helpers ----------
__device__ __forceinline__ unsigned long long pk2(float lo, float hi) {
    unsigned long long r; asm("mov.b64 %0, {%1, %2};" : "=l"(r) : "f"(lo), "f"(hi)); return r;
}
__device__ __forceinline__ unsigned long long bc2(float v) {
    unsigned long long r; asm("mov.b64 %0, {%1, %1};" : "=l"(r) : "f"(v)); return r;
}
__device__ __forceinline__ void fma2(unsigned long long& d, unsigned long long a, unsigned long long b) {
    asm("fma.rn.f32x2 %0, %1, %2, %0;" : "+l"(d) : "l"(a), "l"(b));
}
__device__ __forceinline__ void add2(unsigned long long& d, unsigned long long a) {
    asm("add.rn.f32x2 %0, %0, %1;" : "+l"(d) : "l"(a));
}
__device__ __forceinline__ float2 upk2(unsigned long long v) {
    float lo, hi; asm("mov.b64 {%0, %1}, %2;" : "=f"(lo), "=f"(hi) : "l"(v)); return make_float2(lo, hi);
}

// ---------- warp mma m16n8k16 bf16 ----------
__device__ __forceinline__ void mma16816(float* c, uint32_t a0, uint32_t a1, uint32_t a2,
                                         uint32_t a3, uint32_t b0, uint32_t b1) {
    asm volatile("mma.sync.aligned.m16n8k16.row.col.f32.bf16.bf16.f32 "
                 "{%0,%1,%2,%3}, {%4,%5,%6,%7}, {%8,%9}, {%0,%1,%2,%3};"
                 : "+f"(c[0]), "+f"(c[1]), "+f"(c[2]), "+f"(c[3])
                 : "r"(a0), "r"(a1), "r"(a2), "r"(a3), "r"(b0), "r"(b1));
}

// ---------- prepack weights into mma A-fragment order ----------
__global__ void prepack_frag_kernel(const float* __restrict__ w, uint4* __restrict__ ah,
                                    uint4* __restrict__ al, int CT, int NS, int KREAL) {
    int t = blockIdx.x * 256 + threadIdx.x;
    if (t >= CT * NS * 32) return;
    int lane = t & 31, s = (t >> 5) % NS, ct = t / (NS * 32);
    uint32_t vh[4], vl[4];
#pragma unroll
    for (int i = 0; i < 4; i++) {
        int co = ct * 16 + (lane >> 2) + (i & 1) * 8;
        int k = s * 16 + (lane & 3) * 2 + (i >> 1) * 8;
        float w0 = w[co * KREAL + k], w1 = w[co * KREAL + k + 1];
        uint32_t h0 = f2bf(w0), h1 = f2bf(w1);
        uint32_t l0 = f2bf(w0 - bf2f(h0)), l1 = f2bf(w1 - bf2f(h1));
        vh[i] = h0 | (h1 << 16);
        vl[i] = l0 | (l1 << 16);
    }
    ah[t] = make_uint4(vh[0], vh[1], vh[2], vh[3]);
    al[t] = make_uint4(vl[0], vl[1], vl[2], vl[3]);
}

// ---------- conv via warp mma: packed plane, pad rows pre-zeroed, 2 k-steps/barrier ----------
template <int CIN, int COUT, int NS, int NTMAX, int OCC>
__global__ void __launch_bounds__(256, OCC) conv_mma_kernel(
    const float* __restrict__ gin, const uint4* __restrict__ afh, const uint4* __restrict__ afl,
    const float* __restrict__ bnA, const float* __restrict__ bnB,
    float* __restrict__ gout, float* __restrict__ gsum, float* __restrict__ gsq) {
    constexpr int KREAL = CIN * 9;
    constexpr int CT = COUT / 16;
    constexpr int NS2 = NS / 2;
    constexpr int NROW = 88;
    constexpr int BROW = 12;
    constexpr int BSTG = NROW * BROW;
    constexpr int BSTG2 = 2 * BSTG;
    constexpr int PL = CIN * 121;
    constexpr int OFF_PC   = 2 * 2 * BSTG2 * 4;   // 33792
    constexpr int OFF_OFSP = OFF_PC + PL * 4;
    constexpr int OFF_POF  = OFF_OFSP + (KREAL / 2) * 4;
    constexpr int OFF_RED  = OFF_POF + 81 * 2 + 2;
    extern __shared__ char smc[];
    uint32_t* Bs = (uint32_t*)smc;
    uint32_t* pc   = (uint32_t*)(smc + OFF_PC);
    uint32_t* ofsp = (uint32_t*)(smc + OFF_OFSP);
    unsigned short* pofs = (unsigned short*)(smc + OFF_POF);
    float* red = (float*)(smc + OFF_RED);
    const int tid = threadIdx.x, wid = tid >> 5, lane = tid & 31;
    const int g = lane >> 2, tg = lane & 3;
    const int ct  = (CT == 8) ? wid : (wid & 3);
    const int ntb = (CT == 8) ? 0 : ((wid >> 2) * 6);
    const int ntn = (CT == 8) ? 11 : ((wid >> 2) ? 5 : 6);

    for (int k2 = tid; k2 < KREAL / 2; k2 += 256) {
        int k = 2 * k2;
        int ci0 = k / 9, r0 = k - ci0 * 9;
        int ci1 = (k + 1) / 9, r1 = (k + 1) - ci1 * 9;
        uint32_t o0 = ci0 * 121 + (r0 / 3) * 11 + (r0 % 3);
        uint32_t o1 = ci1 * 121 + (r1 / 3) * 11 + (r1 % 3);
        ofsp[k2] = o0 | (o1 << 16);
    }
    for (int p = tid; p < 81; p += 256) {
        int py = p / 9, px = p - py * 9;
        pofs[p] = (unsigned short)(py * 11 + px);
    }
    for (int i = tid; i < PL; i += 256) pc[i] = 0;
    for (int e = tid; e < 4 * 7 * 16; e += 256) {
        int st4 = e / (7 * 16);
        int rem = e - st4 * 112;
        int p = 81 + rem / 16, kp = rem & 15;
        int sub = kp >> 3, kq = kp & 7;
        Bs[st4 * BSTG2 + sub * BSTG + p * BROW + kq] = 0u;
    }

    float s0 = 0.f, q0 = 0.f, s1 = 0.f, q1 = 0.f;
    const int co0 = ct * 16 + g, co1 = co0 + 8;

    for (int img = blockIdx.x; img < NIMG; img += gridDim.x) {
        __syncthreads();
        const float* ip = gin + (long long)img * (CIN * 81);
        for (int ch = wid; ch < CIN; ch += 8) {
            const float* cp = ip + ch * 81;
            uint32_t* dst = pc + ch * 121;
            float a = bnA[ch], bb = bnB[ch];
            for (int p = lane; p < 81; p += 32) {
                int py = p / 9, px = p - py * 9;
                float v = fmaxf(fmaf(a, cp[p], bb), 0.f);
                uint32_t h = f2bf(v);
                uint32_t l = f2bf(v - bf2f(h));
                dst[(py + 1) * 11 + px + 1] = h | (l << 16);
            }
        }
        __syncthreads();

        float acc[NTMAX][4];
#pragma unroll
        for (int nt = 0; nt < NTMAX; nt++)
#pragma unroll
            for (int i = 0; i < 4; i++) acc[nt][i] = 0.f;

        auto build = [&](int S, int st) {
            uint32_t* bh = Bs + (st * 2 + 0) * BSTG2;
            uint32_t* bl = Bs + (st * 2 + 1) * BSTG2;
            for (int e = tid; e < 81 * 16; e += 256) {
                int p = e >> 4, kp = e & 15;
                uint32_t op = ofsp[S * 16 + kp];
                uint32_t pp = pofs[p];
                uint32_t v0 = pc[(op & 0xFFFFu) + pp];
                uint32_t v1 = pc[(op >> 16) + pp];
                uint32_t bhw = __byte_perm(v0, v1, 0x5410);
                uint32_t blw = __byte_perm(v0, v1, 0x7632);
                int sub = kp >> 3, kq = kp & 7;
                uint32_t off = sub * BSTG + p * BROW + kq;
                bh[off] = bhw;
                bl[off] = blw;
            }
        };

        build(0, 0);
        __syncthreads();

        for (int S = 0; S < NS2; S++) {
            if (S + 1 < NS2) build(S + 1, (S + 1) & 1);
            const uint32_t* cbh = Bs + ((S & 1) * 2 + 0) * BSTG2;
            const uint32_t* cbl = Bs + ((S & 1) * 2 + 1) * BSTG2;
#pragma unroll
            for (int sub = 0; sub < 2; sub++) {
                int s = S * 2 + sub;
                uint4 Ah = afh[(ct * NS + s) * 32 + lane];
                uint4 Al = afl[(ct * NS + s) * 32 + lane];
                const uint32_t* bh = cbh + sub * BSTG;
                const uint32_t* bl = cbl + sub * BSTG;
#pragma unroll
                for (int nt = 0; nt < NTMAX; nt++) {
                    if (nt < ntn) {
                        int row = ((ntb + nt) * 8 + g) * BROW;
                        uint32_t b0 = bh[row + tg], b1 = bh[row + 4 + tg];
                        mma16816(acc[nt], Ah.x, Ah.y, Ah.z, Ah.w, b0, b1);
                        mma16816(acc[nt], Al.x, Al.y, Al.z, Al.w, b0, b1);
                        uint32_t c0 = bl[row + tg], c1 = bl[row + 4 + tg];
                        mma16816(acc[nt], Ah.x, Ah.y, Ah.z, Ah.w, c0, c1);
                    }
                }
            }
            __syncthreads();
        }

        {
            float* op0 = gout + ((long long)img * COUT + co0) * 81;
            float* op1 = gout + ((long long)img * COUT + co1) * 81;
#pragma unroll
            for (int nt = 0; nt < NTMAX; nt++) {
                if (nt < ntn) {
                    int px = (ntb + nt) * 8 + tg * 2;
                    if (px < 81) {
                        op0[px] = acc[nt][0]; s0 += acc[nt][0]; q0 += acc[nt][0] * acc[nt][0];
                        op1[px] = acc[nt][2]; s1 += acc[nt][2]; q1 += acc[nt][2] * acc[nt][2];
                    }
                    if (px + 1 < 81) {
                        op0[px + 1] = acc[nt][1]; s0 += acc[nt][1]; q0 += acc[nt][1] * acc[nt][1];
                        op1[px + 1] = acc[nt][3]; s1 += acc[nt][3]; q1 += acc[nt][3] * acc[nt][3];
                    }
                }
            }
        }
    }

    __syncthreads();
    for (int i = tid; i < 2 * COUT; i += 256) red[i] = 0.f;
    __syncthreads();
    atomicAdd(&red[co0], s0); atomicAdd(&red[COUT + co0], q0);
    atomicAdd(&red[co1], s1); atomicAdd(&red[COUT + co1], q1);
    __syncthreads();
    for (int i = tid; i < COUT; i += 256) {
        atomicAdd(&gsum[i], red[i]);
        atomicAdd(&gsq[i], red[COUT + i]);
    }
}

// ---------- conv1 SIMT (f32x2, fused stats; CG=2) ----------
template <int CIN, int COUT_T, int CG, int IPB>
__global__ void conv_bn_stats_kernel(const float* __restrict__ gin, const float* __restrict__ gw,
                                     float* __restrict__ gout, float* __restrict__ gsum,
                                     float* __restrict__ gsq, int cout_total) {
    constexpr int TASKS = (COUT_T / CG) * 9;
    constexpr int WROW = CIN * 9;
    constexpr int WSTR = (WROW % 2 == 0) ? (WROW + 1) : (WROW + 2);
    constexpr int CG2 = CG / 2;
    extern __shared__ float smf[];
    float* w_s = smf;
    float* in_s = w_s + COUT_T * WSTR;
    float* red = in_s + IPB * CIN * 121;

    const int tx = threadIdx.x, ty = threadIdx.y;
    const int tid = ty * TASKS + tx, nthr = TASKS * IPB;
    const int img = blockIdx.x * IPB + ty;
    const int co_base = blockIdx.y * COUT_T;

    for (int idx = tid; idx < COUT_T * WROW; idx += nthr) {
        int c = idx / WROW, r = idx - c * WROW;
        w_s[c * WSTR + r] = gw[(co_base + c) * WROW + r];
    }
    for (int idx = tid; idx < 2 * COUT_T; idx += nthr) red[idx] = 0.f;
    for (int idx = tid; idx < IPB * CIN * 121; idx += nthr) in_s[idx] = 0.f;
    __syncthreads();
    {
        const float* ip = gin + (long long)img * (CIN * 81);
        float* is = in_s + ty * (CIN * 121);
        for (int idx = tx; idx < CIN * 81; idx += TASKS) {
            int ch = idx / 81, p = idx - ch * 81, y = p / 9, x = p - y * 9;
            is[ch * 121 + (y + 1) * 11 + (x + 1)] = ip[idx];
        }
    }
    __syncthreads();

    const int grp = tx / 9, y = tx - grp * 9;
    unsigned long long acc2[CG2][9];
#pragma unroll
    for (int j = 0; j < CG2; j++)
#pragma unroll
        for (int x = 0; x < 9; x++) acc2[j][x] = 0ull;

    const float* is = in_s + ty * (CIN * 121);
    for (int ci = 0; ci < CIN; ci++) {
        const float* rp = is + ci * 121 + y * 11;
        unsigned long long b0[11], b1[11], b2[11];
#pragma unroll
        for (int x = 0; x < 11; x++) { b0[x] = bc2(rp[x]); b1[x] = bc2(rp[11 + x]); b2[x] = bc2(rp[22 + x]); }
#pragma unroll
        for (int j = 0; j < CG2; j++) {
            const float* wp = w_s + (grp * CG + 2 * j) * WSTR + ci * 9;
            const float* wq = wp + WSTR;
            unsigned long long w[9];
#pragma unroll
            for (int t = 0; t < 9; t++) w[t] = pk2(wp[t], wq[t]);
#pragma unroll
            for (int x = 0; x < 9; x++) {
                fma2(acc2[j][x], b0[x], w[0]); fma2(acc2[j][x], b0[x + 1], w[1]); fma2(acc2[j][x], b0[x + 2], w[2]);
                fma2(acc2[j][x], b1[x], w[3]); fma2(acc2[j][x], b1[x + 1], w[4]); fma2(acc2[j][x], b1[x + 2], w[5]);
                fma2(acc2[j][x], b2[x], w[6]); fma2(acc2[j][x], b2[x + 1], w[7]); fma2(acc2[j][x], b2[x + 2], w[8]);
            }
        }
    }
#pragma unroll
    for (int j = 0; j < CG2; j++) {
        int co0 = co_base + grp * CG + 2 * j;
        float* op0 = gout + ((long long)img * cout_total + co0) * 81 + y * 9;
        float* op1 = op0 + 81;
        unsigned long long s2 = 0ull, q2 = 0ull;
#pragma unroll
        for (int x = 0; x < 9; x++) {
            unsigned long long v = acc2[j][x];
            float2 f = upk2(v);
            op0[x] = f.x; op1[x] = f.y;
            add2(s2, v); fma2(q2, v, v);
        }
        float2 s = upk2(s2), q = upk2(q2);
        atomicAdd(&red[grp * CG + 2 * j], s.x);
        atomicAdd(&red[grp * CG + 2 * j + 1], s.y);
        atomicAdd(&red[COUT_T + grp * CG + 2 * j], q.x);
        atomicAdd(&red[COUT_T + grp * CG + 2 * j + 1], q.y);
    }
    __syncthreads();
    for (int idx = tid; idx < COUT_T; idx += nthr) {
        atomicAdd(&gsum[co_base + idx], red[idx]);
        atomicAdd(&gsq[co_base + idx], red[COUT_T + idx]);
    }
}

// ---------- BN helpers ----------
__global__ void zero_stats_kernel(float* gsum, float* gsq) {
    int t = threadIdx.x;
    if (t < 384) { gsum[t] = 0.f; gsq[t] = 0.f; }
}
__global__ void bn_prep_kernel(const float* gsum, const float* gsq, const float* gamma,
                               const float* beta, float* a, float* b, int C) {
    int c = threadIdx.x;
    if (c < C) {
        float mu = gsum[c] * INV_CNT;
        float var = gsq[c] * INV_CNT - mu * mu;
        float ai = gamma[c] * rsqrtf(var + BN_EPS);
        a[c] = ai; b[c] = beta[c] - mu * ai;
    }
}

// ---------- conv3 -> bf16 hi/lo pairs with BN+ReLU (vectorized, slot-permuted) ----------
__global__ void bf16cvt_kernel(const float* __restrict__ x, const float* __restrict__ bnA,
                               const float* __restrict__ bnB, uint32_t* __restrict__ hi,
                               uint32_t* __restrict__ lo) {
    int idx = blockIdx.x * 256 + threadIdx.x;
    if (idx >= NIMG * 2592) return;
    int img = idx / 2592, q = idx - img * 2592;
    int k0 = q * 4;
    float4 v4 = *(const float4*)(x + (long long)img * KDIM + k0);
    float vv[4] = {v4.x, v4.y, v4.z, v4.w};
    uint32_t hw[2], lw[2];
#pragma unroll
    for (int pi = 0; pi < 2; pi++) {
        int ka = k0 + pi * 2;
        int c0 = ka / 81, c1 = (ka + 1) / 81;
        float a0 = fmaxf(fmaf(bnA[c0], vv[pi * 2], bnB[c0]), 0.f);
        float a1 = fmaxf(fmaf(bnA[c1], vv[pi * 2 + 1], bnB[c1]), 0.f);
        uint32_t h0 = f2bf(a0), h1 = f2bf(a1);
        uint32_t l0 = f2bf(a0 - bf2f(h0)), l1 = f2bf(a1 - bf2f(h1));
        hw[pi] = h0 | (h1 << 16);
        lw[pi] = l0 | (l1 << 16);
    }
    int base = img * 5184;
#pragma unroll
    for (int pi = 0; pi < 2; pi++) {
        int kp = q * 2 + pi;
        int lp = kp & 7;
        int dst = base + (kp & ~7) + (lp & 3) * 2 + (lp >> 2);
        hi[dst] = hw[pi];
        lo[dst] = lw[pi];
    }
}

// ---------- encoder GEMM via mma, split-K=2; partials in [ks][e][m] layout ----------
__global__ void __launch_bounds__(256) enc_mma_kernel(
    const uint32_t* __restrict__ bhig, const uint32_t* __restrict__ blog,
    const uint4* __restrict__ afh, const uint4* __restrict__ afl,
    float* __restrict__ part) {
    __shared__ uint32_t Bs[2][2][64][8];
    const int tid = threadIdx.x, wid = tid >> 5, lane = tid & 31;
    const int g = lane >> 2, tg = lane & 3;
    const int m0 = (blockIdx.x & 127) * 64;
    const int ks = blockIdx.x >> 7;
    const int sbase = ks * 324;

    float acc[8][4];
#pragma unroll
    for (int nt = 0; nt < 8; nt++)
#pragma unroll
        for (int i = 0; i < 4; i++) acc[nt][i] = 0.f;

    const int lrow = (tid & 127) >> 1, lhalf = tid & 1, lterm = tid >> 7;
    const uint32_t* lsrc = (lterm == 0 ? bhig : blog) + (size_t)(m0 + lrow) * 5184
                           + sbase * 8 + lhalf * 4;

    *(uint4*)&Bs[0][lterm][lrow][lhalf * 4] = *(const uint4*)(lsrc);
    __syncthreads();

    uint4 Ah = afh[(wid * 648 + sbase) * 32 + lane];
    uint4 Al = afl[(wid * 648 + sbase) * 32 + lane];

    for (int s = 0; s < 324; s++) {
        int st = s & 1;
        if (s + 1 < 324)
            *(uint4*)&Bs[st ^ 1][lterm][lrow][lhalf * 4] = *(const uint4*)(lsrc + (s + 1) * 8);
        uint4 Ah2, Al2;
        if (s + 1 < 324) {
            Ah2 = afh[(wid * 648 + sbase + s + 1) * 32 + lane];
            Al2 = afl[(wid * 648 + sbase + s + 1) * 32 + lane];
        }
#pragma unroll
        for (int nt = 0; nt < 8; nt++) {
            int col = nt * 8 + g;
            uint2 bh = *(const uint2*)&Bs[st][0][col][tg * 2];
            uint2 bl = *(const uint2*)&Bs[st][1][col][tg * 2];
            mma16816(acc[nt], Ah.x, Ah.y, Ah.z, Ah.w, bh.x, bh.y);
            mma16816(acc[nt], Al.x, Al.y, Al.z, Al.w, bh.x, bh.y);
            mma16816(acc[nt], Ah.x, Ah.y, Ah.z, Ah.w, bl.x, bl.y);
        }
        Ah = Ah2; Al = Al2;
        __syncthreads();
    }

    const int e0 = wid * 16 + g, e1 = e0 + 8;
    float* pp = part + ks * (NIMG * ENCF);
#pragma unroll
    for (int nt = 0; nt < 8; nt++) {
        int m = m0 + nt * 8 + tg * 2;
        pp[e0 * NIMG + m]     = acc[nt][0];
        pp[e0 * NIMG + m + 1] = acc[nt][1];
        pp[e1 * NIMG + m]     = acc[nt][2];
        pp[e1 * NIMG + m + 1] = acc[nt][3];
    }
}

__global__ void combine_enc_kernel(const float* __restrict__ part, const float* __restrict__ enc_b,
                                   float* __restrict__ xcat) {
    int idx = blockIdx.x * 256 + threadIdx.x;
    int e = idx >> 13, m = idx & 8191;
    int b = m >> 7, n = m & 127;
    float v = part[idx] + part[NIMG * ENCF + idx] + enc_b[e];
    xcat[b * (384 * 128) + e * 128 + n] = v;
}

// ---------- X*S and X*S^2 (f-rows split across 2 blocks per batch) ----------
__global__ void xs_kernel(float* __restrict__ xcat, const float* __restrict__ gso) {
    extern __shared__ float smf[];
    float (*Xs)[129] = (float (*)[129])smf;
    float (*Ss)[129] = (float (*)[129])(smf + 64 * 129);
    const int b = blockIdx.x >> 1, fh = blockIdx.x & 1;
    const int tx = threadIdx.x;
    for (int l = 0; l < 64; l++) {
        int idx = tx + l * 256, r = idx >> 7, c = idx & 127;
        Ss[r][c] = gso[b * 16384 + idx];
    }
    for (int l = 0; l < 32; l++) {
        int idx = tx + l * 256, r = idx >> 7, c = idx & 127;
        Xs[r][c] = xcat[b * (384 * 128) + (fh * 64 + r) * 128 + c];
    }
    __syncthreads();
    const int nj = tx & 15, fi = tx >> 4;
    unsigned long long acc2[4][4];
    for (int pass = 0; pass < 2; pass++) {
#pragma unroll
        for (int i = 0; i < 4; i++)
#pragma unroll
            for (int j = 0; j < 4; j++) acc2[i][j] = 0ull;
        for (int n = 0; n < 128; n++) {
            unsigned long long sp[4];
#pragma unroll
            for (int j = 0; j < 4; j++) sp[j] = pk2(Ss[n][nj + 32 * j], Ss[n][nj + 16 + 32 * j]);
#pragma unroll
            for (int i = 0; i < 4; i++) {
                unsigned long long xb = bc2(Xs[fi + 16 * i][n]);
#pragma unroll
                for (int j = 0; j < 4; j++) fma2(acc2[i][j], xb, sp[j]);
            }
        }
        __syncthreads();
        float* gdst = xcat + b * (384 * 128) + (pass + 1) * 16384 + fh * 64 * 128;
#pragma unroll
        for (int i = 0; i < 4; i++)
#pragma unroll
            for (int j = 0; j < 4; j++) {
                float2 v = upk2(acc2[i][j]);
                int f = fi + 16 * i;
                Xs[f][nj + 32 * j] = v.x; Xs[f][nj + 16 + 32 * j] = v.y;
                gdst[f * 128 + nj + 32 * j] = v.x;
                gdst[f * 128 + nj + 16 + 32 * j] = v.y;
            }
        __syncthreads();
    }
}

// ---------- graph-filter GEMM (2 blocks per batch) ----------
__global__ void gfilter_kernel(const float* __restrict__ xcat, const float* __restrict__ W,
                               const float* __restrict__ bias, float* __restrict__ out,
                               int out_stride) {
    extern __shared__ float smf[];
    float (*Ws)[97] = (float (*)[97])smf;
    float (*Xs)[129] = (float (*)[129])(smf + 64 * 97);
    const int b = blockIdx.x >> 1, half = blockIdx.x & 1;
    const int tx = threadIdx.x;
    const int nj = tx & 15, gi = tx >> 4;
    unsigned long long acc2[4][4];
#pragma unroll
    for (int i = 0; i < 4; i++)
#pragma unroll
        for (int j = 0; j < 4; j++) acc2[i][j] = 0ull;
    for (int kt = 0; kt < 4; kt++) {
        for (int l = 0; l < 24; l++) {
            int idx = tx + l * 256;
            int g = idx / 96, kc = idx - g * 96;
            int kg = kt * 96 + kc;
            Ws[g][kc] = W[(kg >> 7) * 16384 + (half * 64 + g) * 128 + (kg & 127)];
        }
        for (int l = 0; l < 48; l++) {
            int idx = tx + l * 256, r = idx >> 7, c = idx & 127;
            Xs[r][c] = xcat[b * (384 * 128) + (kt * 96 + r) * 128 + c];
        }
        __syncthreads();
        for (int kc = 0; kc < 96; kc++) {
            unsigned long long xp[4];
#pragma unroll
            for (int j = 0; j < 4; j++) xp[j] = pk2(Xs[kc][nj + 32 * j], Xs[kc][nj + 16 + 32 * j]);
#pragma unroll
            for (int i = 0; i < 4; i++) {
                unsigned long long wb = bc2(Ws[gi + 16 * i][kc]);
#pragma unroll
                for (int j = 0; j < 4; j++) fma2(acc2[i][j], wb, xp[j]);
            }
        }
        __syncthreads();
    }
#pragma unroll
    for (int i = 0; i < 4; i++) {
        int g = half * 64 + gi + 16 * i;
        float bb = bias[g];
#pragma unroll
        for (int j = 0; j < 4; j++) {
            float2 v = upk2(acc2[i][j]);
            out[b * out_stride + g * 128 + nj + 32 * j] = fmaxf(v.x + bb, 0.f);
            out[b * out_stride + g * 128 + nj + 16 + 32 * j] = fmaxf(v.y + bb, 0.f);
        }
    }
}

// ---------- action head ----------
__global__ void act_kernel(const float* __restrict__ xg2, const float* __restrict__ aw,
                           const float* __restrict__ ab, float* __restrict__ out) {
    extern __shared__ float smf[];
    float* xs = smf;
    float* ws = smf + 16384;
    const int b = blockIdx.x, t = threadIdx.x;
    for (int i = t; i < 16384; i += 256) xs[i] = xg2[b * 16384 + i];
    for (int i = t; i < 640; i += 256) ws[i] = aw[i];
    __syncthreads();
    for (int o = t; o < 640; o += 256) {
        int a = o % 5, n = o / 5;
        float s = ab[a];
        const float* wp = ws + a * 128;
        const float* xp = xs + n;
#pragma unroll 8
        for (int g = 0; g < 128; g++) s = fmaf(xp[g * 128], wp[g], s);
        out[b * 640 + o] = s;
    }
}

// ---------- host launcher ----------
extern "C" void kernel_launch(void* const* d_in, const int* in_sizes, int n_in,
                              void* d_out, int out_size) {
    (void)in_sizes; (void)n_in; (void)out_size;
    const float* states = (const float*)d_in[0];
    const float* gso = (const float*)d_in[1];
    const float* c1_w = (const float*)d_in[2];
    const float* c1_g = (const float*)d_in[4];
    const float* c1_be = (const float*)d_in[5];
    const float* c2_w = (const float*)d_in[6];
    const float* c2_g = (const float*)d_in[8];
    const float* c2_be = (const float*)d_in[9];
    const float* c3_w = (const float*)d_in[10];
    const float* c3_g = (const float*)d_in[12];
    const float* c3_be = (const float*)d_in[13];
    const float* enc_w = (const float*)d_in[14];
    const float* enc_b = (const float*)d_in[15];
    const float* g1_w = (const float*)d_in[16];
    const float* g1_b = (const float*)d_in[17];
    const float* g2_w = (const float*)d_in[18];
    const float* g2_b = (const float*)d_in[19];
    const float* act_w = (const float*)d_in[20];
    const float* act_b = (const float*)d_in[21];
    float* out = (float*)d_out;

    void *p1, *p2, *p3, *pp, *px1, *px2, *pg2, *ps, *pq, *pa, *pb;
    void *a2h, *a2l, *a3h, *a3l, *aeh, *ael, *bhi, *blo;
    cudaGetSymbolAddress(&p1, d_conv1);  cudaGetSymbolAddress(&p2, d_conv2);
    cudaGetSymbolAddress(&p3, d_conv3);  cudaGetSymbolAddress(&pp, d_part);
    cudaGetSymbolAddress(&px1, d_xcat1); cudaGetSymbolAddress(&px2, d_xcat2);
    cudaGetSymbolAddress(&pg2, d_xg2);   cudaGetSymbolAddress(&ps, d_gsum);
    cudaGetSymbolAddress(&pq, d_gsq);    cudaGetSymbolAddress(&pa, d_bnA);
    cudaGetSymbolAddress(&pb, d_bnB);
    cudaGetSymbolAddress(&a2h, d_a2h);   cudaGetSymbolAddress(&a2l, d_a2l);
    cudaGetSymbolAddress(&a3h, d_a3h);   cudaGetSymbolAddress(&a3l, d_a3l);
    cudaGetSymbolAddress(&aeh, d_aeh);   cudaGetSymbolAddress(&ael, d_ael);
    cudaGetSymbolAddress(&bhi, d_bhi);   cudaGetSymbolAddress(&blo, d_blo);
    float *conv1 = (float*)p1, *conv2 = (float*)p2, *conv3 = (float*)p3;
    float *part = (float*)pp;
    float *xcat1 = (float*)px1, *xcat2 = (float*)px2, *xg2 = (float*)pg2;
    float *gsum = (float*)ps, *gsq = (float*)pq, *bnA = (float*)pa, *bnB = (float*)pb;

    const int SM1 = (32 * 29 + 2 * 3 * 121 + 64) * 4;
    const int SMC2 = 33792 + 32 * 121 * 4 + 144 * 4 + 164 + 2 * 64 * 4;    // 50516
    const int SMC3 = 33792 + 64 * 121 * 4 + 288 * 4 + 164 + 2 * 128 * 4;   // 67204
    const int XS_SMEM = (64 * 129 + 128 * 129) * 4;
    const int GF_SMEM = (64 * 97 + 96 * 129) * 4;
    const int ACT_SMEM = (16384 + 640) * 4;

    cudaFuncSetAttribute(conv_bn_stats_kernel<3, 32, 2, 2>, cudaFuncAttributeMaxDynamicSharedMemorySize, SM1);
    cudaFuncSetAttribute(conv_mma_kernel<32, 64, 18, 6, 4>, cudaFuncAttributeMaxDynamicSharedMemorySize, SMC2);
    cudaFuncSetAttribute(conv_mma_kernel<64, 128, 36, 11, 3>, cudaFuncAttributeMaxDynamicSharedMemorySize, SMC3);
    cudaFuncSetAttribute(xs_kernel, cudaFuncAttributeMaxDynamicSharedMemorySize, XS_SMEM);
    cudaFuncSetAttribute(gfilter_kernel, cudaFuncAttributeMaxDynamicSharedMemorySize, GF_SMEM);
    cudaFuncSetAttribute(act_kernel, cudaFuncAttributeMaxDynamicSharedMemorySize, ACT_SMEM);

    zero_stats_kernel<<<1, 384>>>(gsum, gsq);
    prepack_frag_kernel<<<(4 * 18 * 32 + 255) / 256, 256>>>(c2_w, (uint4*)a2h, (uint4*)a2l, 4, 18, 288);
    prepack_frag_kernel<<<(8 * 36 * 32 + 255) / 256, 256>>>(c3_w, (uint4*)a3h, (uint4*)a3l, 8, 36, 576);
    prepack_frag_kernel<<<648, 256>>>(enc_w, (uint4*)aeh, (uint4*)ael, 8, 648, 10368);

    conv_bn_stats_kernel<3, 32, 2, 2>
        <<<dim3(NIMG / 2, 1), dim3(144, 2), SM1>>>(states, c1_w, conv1, gsum, gsq, 32);
    bn_prep_kernel<<<1, 128>>>(gsum, gsq, c1_g, c1_be, bnA, bnB, 32);

    conv_mma_kernel<32, 64, 18, 6, 4><<<592, 256, SMC2>>>(conv1, (const uint4*)a2h, (const uint4*)a2l,
                                                          bnA, bnB, conv2, gsum + 128, gsq + 128);
    bn_prep_kernel<<<1, 128>>>(gsum + 128, gsq + 128, c2_g, c2_be, bnA + 128, bnB + 128, 64);

    conv_mma_kernel<64, 128, 36, 11, 3><<<444, 256, SMC3>>>(conv2, (const uint4*)a3h, (const uint4*)a3l,
                                                            bnA + 128, bnB + 128, conv3,
                                                            gsum + 256, gsq + 256);
    bn_prep_kernel<<<1, 128>>>(gsum + 256, gsq + 256, c3_g, c3_be, bnA + 256, bnB + 256, 128);

    bf16cvt_kernel<<<(NIMG * 2592 + 255) / 256, 256>>>(conv3, bnA + 256, bnB + 256,
                                                       (uint32_t*)bhi, (uint32_t*)blo);
    enc_mma_kernel<<<256, 256>>>((const uint32_t*)bhi, (const uint32_t*)blo,
                                 (const uint4*)aeh, (const uint4*)ael, part);
    combine_enc_kernel<<<4096, 256>>>(part, enc_b, xcat1);

    xs_kernel<<<BATCH * 2, 256, XS_SMEM>>>(xcat1, gso);
    gfilter_kernel<<<BATCH * 2, 256, GF_SMEM>>>(xcat1, g1_w, g1_b, xcat2, 384 * 128);
    xs_kernel<<<BATCH * 2, 256, XS_SMEM>>>(xcat2, gso);
    gfilter_kernel<<<BATCH * 2, 256, GF_SMEM>>>(xcat2, g2_w, g2_b, xg2, 128 * 128);
    act_kernel<<<BATCH, 256, ACT_SMEM>>>(xg2, act_w, act_b, out);
}